// round 14
// baseline (speedup 1.0000x reference)
#include <cuda_runtime.h>
#include <cuda_bf16.h>
#include <cuda_fp16.h>
#include <math.h>
#include <stdint.h>
#include <string.h>

// ---------------------------------------------------------------------------
// NeuralSplineFlow forward — bin-directed derived-knot table (R13) with a
// ONE-WAVE table build (R14): fine grid delta 1/128 -> 1/64 cuts the
// table_build grid from 160 to 96 blocks (<=148 SMs, 1 CTA/SM at 204KB smem),
// halving its cost. Flow kernel unchanged (5 divergent loads/sample/layer).
// ---------------------------------------------------------------------------

#define BATCH   262144
#define NLAYER  16
#define HDIM    128
#define NBINS   8
#define PMVAL   23
#define TBV     3.0f
#define MINWV   0.001f
#define MINDV   0.001f
#define LUEPS   0.001f
#define INV_SQH 0.08838834764831843f   // 1/sqrt(128)

// dual-resolution table
#define NODES_F 513                    // [-4,4], delta 1/64
#define NODES_C 129                    // [-16,16], delta 1/4
#define NODES_T (NODES_F + NODES_C)    // 642
#define BLKS_PER_LAYER 6               // ceil(642/128) -> 96 blocks total
#define TINVD_F  64.0f
#define TINVD_C  4.0f
#define TDELTA_F 0.015625f
#define TDELTA_C 0.25f

// SMEM geometry for the table-build (mma) kernel
#define KSTRIDE   136
#define ROWB      (KSTRIDE * 2)
#define ACT_BYTES (HDIM * ROWB)          // 34816
#define WMAT_ELEMS (HDIM * KSTRIDE)
#define WSLOT_BYTES (2 * ACT_BYTES)      // 69632
#define WF_STRIDE 40
#define WF_HALF   (HDIM * WF_STRIDE)
#define WF_BYTES  (2 * WF_HALF * 2)

#define OFF_ACTHI 0
#define OFF_ACTLO 34816
#define OFF_SLOT0 69632
#define OFF_SLOT1 139264
#define OFF_P1    139264
#define DYN_SMEM  208896

// ----------------------------- device scratch ------------------------------
__device__ __align__(16) uint16_t g_Wimg[NLAYER * 4 * 2 * WMAT_ELEMS];
__device__ __align__(16) uint16_t g_Wfimg[NLAYER * 2 * WF_HALF];
__device__ __align__(16) float g_ktF[NLAYER * NODES_F * 24];
__device__ __align__(16) float g_ktC[NLAYER * NODES_C * 24];
__device__ __align__(16) float g_s1F[NLAYER * NODES_F * 12];
__device__ __align__(16) float g_s1C[NLAYER * NODES_C * 12];
__device__ __align__(16) float g_kdF[NLAYER * NODES_F * 64];
__device__ __align__(16) float g_kdC[NLAYER * NODES_C * 64];
__device__ float g_cw0[NLAYER * 9];
__device__ float g_w0[NLAYER * 8];
__device__ float g_ch0[NLAYER * 9];
__device__ float g_h0[NLAYER * 8];
__device__ float g_d0[NLAYER * 9];
__device__ float g_invW[NLAYER * 4];
__device__ float g_ldinit;

// ----------------------------- PTX helpers ---------------------------------
__device__ __forceinline__ uint32_t smem_u32(const void* p) {
    uint32_t a;
    asm("{ .reg .u64 t; cvta.to.shared.u64 t, %1; cvt.u32.u64 %0, t; }"
        : "=r"(a) : "l"(p));
    return a;
}
__device__ __forceinline__ void ldmA4(uint32_t a[4], uint32_t addr) {
    asm volatile("ldmatrix.sync.aligned.m8n8.x4.shared.b16 {%0,%1,%2,%3}, [%4];"
        : "=r"(a[0]), "=r"(a[1]), "=r"(a[2]), "=r"(a[3]) : "r"(addr));
}
__device__ __forceinline__ void ldmB4t(uint32_t b[4], uint32_t addr) {
    asm volatile("ldmatrix.sync.aligned.m8n8.x4.trans.shared.b16 {%0,%1,%2,%3}, [%4];"
        : "=r"(b[0]), "=r"(b[1]), "=r"(b[2]), "=r"(b[3]) : "r"(addr));
}
__device__ __forceinline__ void mmabf(float d[4], const uint32_t a[4],
                                      uint32_t b0, uint32_t b1) {
    asm volatile("mma.sync.aligned.m16n8k16.row.col.f32.bf16.bf16.f32 "
        "{%0,%1,%2,%3}, {%4,%5,%6,%7}, {%8,%9}, {%0,%1,%2,%3};"
        : "+f"(d[0]), "+f"(d[1]), "+f"(d[2]), "+f"(d[3])
        : "r"(a[0]), "r"(a[1]), "r"(a[2]), "r"(a[3]), "r"(b0), "r"(b1));
}
__device__ __forceinline__ void cpasync16(uint32_t dst, const void* src) {
    asm volatile("cp.async.cg.shared.global [%0], [%1], 16;"
                 :: "r"(dst), "l"(src));
}
#define CP_COMMIT() asm volatile("cp.async.commit_group;" ::: "memory")
#define CP_WAIT0()  asm volatile("cp.async.wait_group 0;" ::: "memory")

__device__ __forceinline__ float pack_h2(float a, float b) {
    __half2 h = __floats2half2_rn(a, b);
    uint32_t u;
    memcpy(&u, &h, 4);
    return __uint_as_float(u);
}
__device__ __forceinline__ void unpack_h2(float p, float& lo, float& hi) {
    uint32_t u = __float_as_uint(p);
    __half2 h;
    memcpy(&h, &u, 4);
    lo = __low2float(h);
    hi = __high2float(h);
}

// ----------------------------- math helpers --------------------------------
__device__ __forceinline__ float softplusf(float x) {
    return fmaxf(x, 0.f) + log1pf(expf(-fabsf(x)));
}
__device__ __forceinline__ float softplus_fast(float x) {
    return fmaxf(x, 0.f) + __logf(1.f + __expf(-fabsf(x)));
}

__device__ void build_params(const float* uw, const float* uh, const float* ud,
                             float* cw, float* w, float* ch, float* hh, float* dd) {
    {
        float mx = uw[0];
        #pragma unroll
        for (int k = 1; k < NBINS; k++) mx = fmaxf(mx, uw[k]);
        float e[NBINS]; float s = 0.f;
        #pragma unroll
        for (int k = 0; k < NBINS; k++) { e[k] = expf(uw[k] - mx); s += e[k]; }
        float inv = 1.f / s;
        cw[0] = -TBV; float cum = 0.f;
        #pragma unroll
        for (int k = 0; k < NBINS; k++) {
            float wk = MINWV + (1.f - MINWV * NBINS) * e[k] * inv;
            cum += wk;
            cw[k + 1] = 2.f * TBV * cum - TBV;
        }
        cw[NBINS] = TBV;
        #pragma unroll
        for (int k = 0; k < NBINS; k++) w[k] = cw[k + 1] - cw[k];
    }
    {
        float mx = uh[0];
        #pragma unroll
        for (int k = 1; k < NBINS; k++) mx = fmaxf(mx, uh[k]);
        float e[NBINS]; float s = 0.f;
        #pragma unroll
        for (int k = 0; k < NBINS; k++) { e[k] = expf(uh[k] - mx); s += e[k]; }
        float inv = 1.f / s;
        ch[0] = -TBV; float cum = 0.f;
        #pragma unroll
        for (int k = 0; k < NBINS; k++) {
            float hk = MINWV + (1.f - MINWV * NBINS) * e[k] * inv;
            cum += hk;
            ch[k + 1] = 2.f * TBV * cum - TBV;
        }
        ch[NBINS] = TBV;
        #pragma unroll
        for (int k = 0; k < NBINS; k++) hh[k] = ch[k + 1] - ch[k];
    }
    dd[0] = 1.0f;
    #pragma unroll
    for (int k = 0; k < 7; k++) dd[k + 1] = MINDV + softplusf(ud[k]);
    dd[NBINS] = 1.0f;
}

__device__ __forceinline__ void rqs_reg(float y, const float cw[9], const float w[8],
                                        const float ch[9], const float hh[8],
                                        const float dd[9], float& xout, float& ldout) {
    bool inside = (y >= -TBV) && (y <= TBV);
    float yc = fminf(fmaxf(y, -TBV), TBV);
    float yk = ch[0], hk = hh[0], xk = cw[0], wk = w[0], dk = dd[0], dk1 = dd[1];
    #pragma unroll
    for (int k = 1; k < NBINS; k++) {
        bool c = yc >= ch[k];
        yk  = c ? ch[k]     : yk;
        hk  = c ? hh[k]     : hk;
        xk  = c ? cw[k]     : xk;
        wk  = c ? w[k]      : wk;
        dk  = c ? dd[k]     : dk;
        dk1 = c ? dd[k + 1] : dk1;
    }
    float sk = __fdividef(hk, wk);
    float dy = yc - yk;
    float t2 = dk + dk1 - 2.f * sk;
    float qa = dy * t2 + hk * (sk - dk);
    float qb = hk * dk - dy * t2;
    float qc = -sk * dy;
    float disc = fmaxf(qb * qb - 4.f * qa * qc, 0.f);
    float theta = __fdividef(2.f * qc, -qb - sqrtf(disc));
    float xo = theta * wk + xk;
    float om = 1.f - theta;
    float denom = sk + t2 * theta * om;
    float dnum = sk * sk * (dk1 * theta * theta + 2.f * sk * theta * om + dk * om * om);
    float ldf = __logf(__fdividef(dnum, denom * denom));
    xout  = inside ? xo : y;
    ldout = inside ? -ldf : 0.f;
}

__device__ __forceinline__ void rqs_knots(float y, const float cw[9], const float ch[9],
                                          const float dd[9], float& xout, float& ldout) {
    bool inside = (y >= -TBV) && (y <= TBV);
    float yc = fminf(fmaxf(y, -TBV), TBV);
    float yk = ch[0], yk1 = ch[1], xk = cw[0], xk1 = cw[1], dk = dd[0], dk1 = dd[1];
    #pragma unroll
    for (int k = 1; k < NBINS; k++) {
        bool c = yc >= ch[k];
        yk  = c ? ch[k]     : yk;
        yk1 = c ? ch[k + 1] : yk1;
        xk  = c ? cw[k]     : xk;
        xk1 = c ? cw[k + 1] : xk1;
        dk  = c ? dd[k]     : dk;
        dk1 = c ? dd[k + 1] : dk1;
    }
    float hk = yk1 - yk, wk = xk1 - xk;
    float sk = __fdividef(hk, wk);
    float dy = yc - yk;
    float t2 = dk + dk1 - 2.f * sk;
    float qa = dy * t2 + hk * (sk - dk);
    float qb = hk * dk - dy * t2;
    float qc = -sk * dy;
    float disc = fmaxf(qb * qb - 4.f * qa * qc, 0.f);
    float theta = __fdividef(2.f * qc, -qb - sqrtf(disc));
    float xo = theta * wk + xk;
    float om = 1.f - theta;
    float denom = sk + t2 * theta * om;
    float dnum = sk * sk * (dk1 * theta * theta + 2.f * sk * theta * om + dk * om * om);
    float ldf = __logf(__fdividef(dnum, denom * denom));
    xout  = inside ? xo : y;
    ldout = inside ? -ldf : 0.f;
}

__device__ __forceinline__ void knots_from_p1(const float* p1, float cw[9],
                                              float ch[9], float dd[9]) {
    float uw[8], uh[8];
    #pragma unroll
    for (int k = 0; k < 8; k++) { uw[k] = p1[k] * INV_SQH; uh[k] = p1[8 + k] * INV_SQH; }
    float mw = uw[0], mh = uh[0];
    #pragma unroll
    for (int k = 1; k < 8; k++) { mw = fmaxf(mw, uw[k]); mh = fmaxf(mh, uh[k]); }
    float ew[8], eh[8], sw = 0.f, sh = 0.f;
    #pragma unroll
    for (int k = 0; k < 8; k++) {
        ew[k] = __expf(uw[k] - mw); sw += ew[k];
        eh[k] = __expf(uh[k] - mh); sh += eh[k];
    }
    float iw = __fdividef(1.f - MINWV * NBINS, sw);
    float ih = __fdividef(1.f - MINWV * NBINS, sh);
    cw[0] = -TBV; ch[0] = -TBV;
    float cumw = 0.f, cumh = 0.f;
    #pragma unroll
    for (int k = 0; k < 7; k++) {
        cumw += MINWV + iw * ew[k];
        cumh += MINWV + ih * eh[k];
        cw[k + 1] = fmaf(2.f * TBV, cumw, -TBV);
        ch[k + 1] = fmaf(2.f * TBV, cumh, -TBV);
    }
    cw[8] = TBV; ch[8] = TBV;
    dd[0] = 1.f; dd[8] = 1.f;
    #pragma unroll
    for (int k = 0; k < 7; k++) dd[k + 1] = MINDV + softplus_fast(p1[16 + k]);
}

__device__ __forceinline__ void split2(float a, float b, uint32_t& hi, uint32_t& lo) {
    __nv_bfloat16 ah = __float2bfloat16(a), bh = __float2bfloat16(b);
    __nv_bfloat16 al = __float2bfloat16(a - __bfloat162float(ah));
    __nv_bfloat16 bl = __float2bfloat16(b - __bfloat162float(bh));
    hi = (uint32_t)__bfloat16_as_ushort(ah) | ((uint32_t)__bfloat16_as_ushort(bh) << 16);
    lo = (uint32_t)__bfloat16_as_ushort(al) | ((uint32_t)__bfloat16_as_ushort(bl) << 16);
}

// ------------------------------ setup kernels ------------------------------
// n-fastest => coalesced STORES (scattered reads hit L2).
__global__ void build_wimg_kernel(const float* __restrict__ Wres,
                                  const float* __restrict__ Wf) {
    const int total1 = NLAYER * 4 * HDIM * KSTRIDE;
    for (int t = blockIdx.x * blockDim.x + threadIdx.x; t < total1;
         t += gridDim.x * blockDim.x) {
        int n  = t % KSTRIDE;
        int k  = (t / KSTRIDE) % HDIM;
        int mg = t / (KSTRIDE * HDIM);
        float v = (n < HDIM) ? Wres[mg * 16384 + n * HDIM + k] : 0.f;
        __nv_bfloat16 h = __float2bfloat16(v);
        __nv_bfloat16 l = __float2bfloat16(v - __bfloat162float(h));
        int base = (mg * 2) * WMAT_ELEMS + k * KSTRIDE + n;
        g_Wimg[base]              = __bfloat16_as_ushort(h);
        g_Wimg[base + WMAT_ELEMS] = __bfloat16_as_ushort(l);
    }
    const int total2 = NLAYER * HDIM * WF_STRIDE;
    for (int t = blockIdx.x * blockDim.x + threadIdx.x; t < total2;
         t += gridDim.x * blockDim.x) {
        int n  = t % WF_STRIDE;
        int k  = (t / WF_STRIDE) % HDIM;
        int ly = t / (WF_STRIDE * HDIM);
        float v = (n < PMVAL) ? Wf[(ly * (2 * PMVAL) + PMVAL + n) * HDIM + k] : 0.f;
        __nv_bfloat16 h = __float2bfloat16(v);
        __nv_bfloat16 l = __float2bfloat16(v - __bfloat162float(h));
        int base = (ly * 2) * WF_HALF + k * WF_STRIDE + n;
        g_Wfimg[base]           = __bfloat16_as_ushort(h);
        g_Wfimg[base + WF_HALF] = __bfloat16_as_ushort(l);
    }
}

__global__ void setup_kernel(const float* __restrict__ made_bf,
                             const float* __restrict__ lu_lower,
                             const float* __restrict__ lu_upper,
                             const float* __restrict__ lu_diag) {
    __shared__ float sldl[NLAYER];
    int i = threadIdx.x;
    if (i < NLAYER) {
        const float* bfL = made_bf + i * (2 * PMVAL);
        float uw[8], uh[8], ud[7];
        #pragma unroll
        for (int k = 0; k < 8; k++) { uw[k] = bfL[k] * INV_SQH; uh[k] = bfL[8 + k] * INV_SQH; }
        #pragma unroll
        for (int k = 0; k < 7; k++) ud[k] = bfL[16 + k];
        build_params(uw, uh, ud, g_cw0 + 9 * i, g_w0 + 8 * i,
                     g_ch0 + 9 * i, g_h0 + 8 * i, g_d0 + 9 * i);
        float l = lu_lower[i], u = lu_upper[i];
        float d0 = softplusf(lu_diag[2 * i]) + LUEPS;
        float d1 = softplusf(lu_diag[2 * i + 1]) + LUEPS;
        float invdet = 1.f / (d0 * d1);
        g_invW[4 * i + 0] = (l * u + d1) * invdet;
        g_invW[4 * i + 1] = -u * invdet;
        g_invW[4 * i + 2] = -l * d0 * invdet;
        g_invW[4 * i + 3] = d0 * invdet;
        sldl[i] = logf(d0) + logf(d1);
    }
    __syncthreads();
    if (i == 0) {
        float s = 0.f;
        for (int j = 0; j < NLAYER; j++) s += sldl[j];
        g_ldinit = -s;
    }
}

// ------------------------- table-build (mma) kernel -------------------------
__device__ __forceinline__ void prefetch_w(uint32_t dst_u, const uint16_t* gsrc,
                                           int chunks, int tid) {
    const char* s = (const char*)gsrc;
    for (int i = tid; i < chunks; i += 256)
        cpasync16(dst_u + i * 16, s + i * 16);
    CP_COMMIT();
}

__global__ void __launch_bounds__(256, 1)
table_build_kernel(const float* __restrict__ made_W0,
                   const float* __restrict__ made_b0,
                   const float* __restrict__ made_bres,
                   const float* __restrict__ made_bf) {
    extern __shared__ char dynsm[];
    __shared__ float s_bias[4][HDIM];
    __shared__ float s_out0[HDIM];
    __shared__ float s_w0col[HDIM], s_b0[HDIM];

    const int layer = blockIdx.x / BLKS_PER_LAYER;
    const int tile  = blockIdx.x % BLKS_PER_LAYER;
    const int tid   = threadIdx.x;
    const int lane  = tid & 31;
    const int w     = tid >> 5;

    const uint32_t base_u  = smem_u32(dynsm);
    const uint32_t actHi_u = base_u + OFF_ACTHI;
    const uint32_t slot_u[2] = { base_u + OFF_SLOT0, base_u + OFF_SLOT1 };

    prefetch_w(slot_u[0], g_Wimg + (size_t)(layer * 4) * (2 * WMAT_ELEMS),
               WSLOT_BYTES / 16, tid);

    if (tid < HDIM) {
        s_w0col[tid] = made_W0[(layer * HDIM + tid) * 2];
        s_b0[tid]    = made_b0[layer * HDIM + tid];
        int node = tile * HDIM + tid;
        float x = (node < NODES_F)
                ? (-4.f  + (float)node * TDELTA_F)
                : (-16.f + (float)(node - NODES_F) * TDELTA_C);
        s_out0[tid] = x;
    }
    for (int i = tid; i < 4 * HDIM; i += 256)
        s_bias[i >> 7][i & 127] = made_bres[layer * 4 * HDIM + i];
    __syncthreads();

    const int r0 = w * 16 + (lane >> 2);
    const int r1 = r0 + 8;
    const int cB = (lane & 3) * 2;
    const uint32_t o0 = (uint32_t)r0 * ROWB + cB * 2;
    const uint32_t o1 = (uint32_t)r1 * ROWB + cB * 2;

    float H[64];
    {
        float oa = s_out0[r0], ob = s_out0[r1];
        #pragma unroll
        for (int t = 0; t < 16; t++) {
            int c = t * 8 + cB;
            float2 wc = *(const float2*)&s_w0col[c];
            float2 bc = *(const float2*)&s_b0[c];
            float h0 = fmaf(oa, wc.x, bc.x), h1 = fmaf(oa, wc.y, bc.y);
            float h2 = fmaf(ob, wc.x, bc.x), h3 = fmaf(ob, wc.y, bc.y);
            H[t * 4] = h0; H[t * 4 + 1] = h1; H[t * 4 + 2] = h2; H[t * 4 + 3] = h3;
            uint32_t hi0, lo0, hi1, lo1;
            split2(fmaxf(h0, 0.f), fmaxf(h1, 0.f), hi0, lo0);
            split2(fmaxf(h2, 0.f), fmaxf(h3, 0.f), hi1, lo1);
            *(uint32_t*)(dynsm + OFF_ACTHI + o0 + t * 16) = hi0;
            *(uint32_t*)(dynsm + OFF_ACTHI + o1 + t * 16) = hi1;
            *(uint32_t*)(dynsm + OFF_ACTLO + o0 + t * 16) = lo0;
            *(uint32_t*)(dynsm + OFF_ACTLO + o1 + t * 16) = lo1;
        }
    }
    CP_WAIT0();
    __syncthreads();

    const uint32_t aHiBase = actHi_u + (uint32_t)(w * 16 + (lane & 15)) * ROWB
                             + ((lane >> 4) * 16);
    const uint32_t aLoBase = aHiBase + ACT_BYTES;
    const uint32_t bOff    = (uint32_t)(lane & 15) * ROWB + ((lane >> 4) * 16);
    const uint32_t wfOff   = (uint32_t)(lane & 15) * (WF_STRIDE * 2) + ((lane >> 4) * 16);

    #pragma unroll 1
    for (int g = 0; g < 4; g++) {
        if (g < 3)
            prefetch_w(slot_u[(g + 1) & 1],
                       g_Wimg + (size_t)(layer * 4 + g + 1) * (2 * WMAT_ELEMS),
                       WSLOT_BYTES / 16, tid);
        else
            prefetch_w(slot_u[0], g_Wfimg + (size_t)layer * (2 * WF_HALF),
                       WF_BYTES / 16, tid);

        __syncwarp();
        uint32_t Ah[8][4], Al[8][4];
        #pragma unroll
        for (int kc = 0; kc < 8; kc++) {
            ldmA4(Ah[kc], aHiBase + kc * 32);
            ldmA4(Al[kc], aLoBase + kc * 32);
        }
        const uint32_t wbase = slot_u[g & 1] + bOff;

        #pragma unroll
        for (int tp = 0; tp < 8; tp++) {
            float D0[4] = {0.f, 0.f, 0.f, 0.f};
            float D1[4] = {0.f, 0.f, 0.f, 0.f};
            #pragma unroll
            for (int kc = 0; kc < 8; kc++) {
                uint32_t bh[4], bl[4];
                ldmB4t(bh, wbase + kc * (16 * ROWB) + tp * 32);
                ldmB4t(bl, wbase + ACT_BYTES + kc * (16 * ROWB) + tp * 32);
                mmabf(D0, Ah[kc], bh[0], bh[1]);
                mmabf(D0, Al[kc], bh[0], bh[1]);
                mmabf(D0, Ah[kc], bl[0], bl[1]);
                mmabf(D1, Ah[kc], bh[2], bh[3]);
                mmabf(D1, Al[kc], bh[2], bh[3]);
                mmabf(D1, Ah[kc], bl[2], bl[3]);
            }
            #pragma unroll
            for (int q = 0; q < 2; q++) {
                const int t = tp * 2 + q;
                float* D = q ? D1 : D0;
                float2 bb = *(const float2*)&s_bias[g][t * 8 + cB];
                float v0, v1, v2, v3;
                if ((g & 1) == 0) {
                    v0 = fmaxf(D[0] + bb.x, 0.f);
                    v1 = fmaxf(D[1] + bb.y, 0.f);
                    v2 = fmaxf(D[2] + bb.x, 0.f);
                    v3 = fmaxf(D[3] + bb.y, 0.f);
                } else {
                    float n0 = H[t * 4]     + D[0] + bb.x;
                    float n1 = H[t * 4 + 1] + D[1] + bb.y;
                    float n2 = H[t * 4 + 2] + D[2] + bb.x;
                    float n3 = H[t * 4 + 3] + D[3] + bb.y;
                    H[t * 4] = n0; H[t * 4 + 1] = n1;
                    H[t * 4 + 2] = n2; H[t * 4 + 3] = n3;
                    if (g == 3) { v0 = n0; v1 = n1; v2 = n2; v3 = n3; }
                    else { v0 = fmaxf(n0, 0.f); v1 = fmaxf(n1, 0.f);
                           v2 = fmaxf(n2, 0.f); v3 = fmaxf(n3, 0.f); }
                }
                uint32_t hi0, lo0, hi1, lo1;
                split2(v0, v1, hi0, lo0);
                split2(v2, v3, hi1, lo1);
                *(uint32_t*)(dynsm + OFF_ACTHI + o0 + t * 16) = hi0;
                *(uint32_t*)(dynsm + OFF_ACTHI + o1 + t * 16) = hi1;
                *(uint32_t*)(dynsm + OFF_ACTLO + o0 + t * 16) = lo0;
                *(uint32_t*)(dynsm + OFF_ACTLO + o1 + t * 16) = lo1;
            }
        }
        CP_WAIT0();
        __syncthreads();
    }

    // Wf GEMM
    {
        __syncwarp();
        uint32_t Ah[8][4], Al[8][4];
        #pragma unroll
        for (int kc = 0; kc < 8; kc++) {
            ldmA4(Ah[kc], aHiBase + kc * 32);
            ldmA4(Al[kc], aLoBase + kc * 32);
        }
        const uint32_t wfb = slot_u[0] + wfOff;
        float* p1 = (float*)(dynsm + OFF_P1);
        #pragma unroll
        for (int tp = 0; tp < 2; tp++) {
            float D0[4] = {0.f, 0.f, 0.f, 0.f};
            float D1[4] = {0.f, 0.f, 0.f, 0.f};
            #pragma unroll
            for (int kc = 0; kc < 8; kc++) {
                uint32_t bh[4], bl[4];
                ldmB4t(bh, wfb + kc * (16 * WF_STRIDE * 2) + tp * 32);
                ldmB4t(bl, wfb + 2 * WF_HALF + kc * (16 * WF_STRIDE * 2) + tp * 32);
                mmabf(D0, Ah[kc], bh[0], bh[1]);
                mmabf(D0, Al[kc], bh[0], bh[1]);
                mmabf(D0, Ah[kc], bl[0], bl[1]);
                mmabf(D1, Ah[kc], bh[2], bh[3]);
                mmabf(D1, Al[kc], bh[2], bh[3]);
                mmabf(D1, Ah[kc], bl[2], bl[3]);
            }
            int c0 = tp * 16 + cB;
            p1[r0 * 26 + c0] = D0[0]; p1[r0 * 26 + c0 + 1] = D0[1];
            p1[r1 * 26 + c0] = D0[2]; p1[r1 * 26 + c0 + 1] = D0[3];
            if (tp == 0) {
                p1[r0 * 26 + c0 + 8] = D1[0]; p1[r0 * 26 + c0 + 9] = D1[1];
                p1[r1 * 26 + c0 + 8] = D1[2]; p1[r1 * 26 + c0 + 9] = D1[3];
            }
        }
    }
    __syncthreads();

    if (tid < HDIM) {
        int node = tile * HDIM + tid;
        if (node < NODES_T) {
            const float* p1r = (const float*)(dynsm + OFF_P1) + tid * 26;
            const float* bf1 = made_bf + layer * (2 * PMVAL) + PMVAL;
            float uw[8], uh[8], ud[7];
            #pragma unroll
            for (int k = 0; k < 8; k++) {
                uw[k] = (p1r[k]     + bf1[k])     * INV_SQH;
                uh[k] = (p1r[8 + k] + bf1[8 + k]) * INV_SQH;
            }
            #pragma unroll
            for (int k = 0; k < 7; k++) ud[k] = p1r[16 + k] + bf1[16 + k];
            float cw[9], ww[8], chh[9], hh2[8], dd[9];
            build_params(uw, uh, ud, cw, ww, chh, hh2, dd);
            float* row = (node < NODES_F)
                ? g_ktF + ((size_t)layer * NODES_F + node) * 24
                : g_ktC + ((size_t)layer * NODES_C + (node - NODES_F)) * 24;
            #pragma unroll
            for (int k = 0; k < 7; k++) {
                row[k]      = cw[k + 1];
                row[7 + k]  = chh[k + 1];
                row[14 + k] = dd[k + 1];
            }
            row[21] = 0.f; row[22] = 0.f; row[23] = 0.f;
        }
    }
}

// pack: 8 threads per node; thread p writes KD entry p, p==0 also writes S1.
__global__ void pack_kernel() {
    int t = blockIdx.x * blockDim.x + threadIdx.x;
    int nodeIdx = t >> 3;
    int p = t & 7;
    if (nodeIdx >= NLAYER * NODES_T) return;
    int layer = nodeIdx / NODES_T;
    int node  = nodeIdx % NODES_T;
    bool fine = (node < NODES_F);
    int ni = fine ? node : node - NODES_F;
    int nn = fine ? min(ni + 1, NODES_F - 1) : min(ni + 1, NODES_C - 1);
    const float* cur = fine ? g_ktF + ((size_t)layer * NODES_F + ni) * 24
                            : g_ktC + ((size_t)layer * NODES_C + ni) * 24;
    const float* nxt = fine ? g_ktF + ((size_t)layer * NODES_F + nn) * 24
                            : g_ktC + ((size_t)layer * NODES_C + nn) * 24;

    if (p == 0) {
        float s1[12];
        #pragma unroll
        for (int k = 0; k < 7; k++) s1[k] = cur[7 + k];
        float dch[7];
        #pragma unroll
        for (int k = 0; k < 7; k++) dch[k] = nxt[7 + k] - cur[7 + k];
        s1[7]  = pack_h2(dch[0], dch[1]);
        s1[8]  = pack_h2(dch[2], dch[3]);
        s1[9]  = pack_h2(dch[4], dch[5]);
        s1[10] = pack_h2(dch[6], 0.f);
        s1[11] = 0.f;
        float* s1dst = fine ? g_s1F + ((size_t)layer * NODES_F + ni) * 12
                            : g_s1C + ((size_t)layer * NODES_C + ni) * 12;
        #pragma unroll
        for (int q = 0; q < 3; q++)
            ((float4*)s1dst)[q] = ((const float4*)s1)[q];
    }

    float cwc_p  = (p == 0) ? -TBV : cur[p - 1];
    float cwc_p1 = (p == 7) ?  TBV : cur[p];
    float cwn_p  = (p == 0) ? -TBV : nxt[p - 1];
    float cwn_p1 = (p == 7) ?  TBV : nxt[p];
    float dfc_p  = (p == 0) ? 1.f : cur[14 + p - 1];
    float dfc_p1 = (p == 7) ? 1.f : cur[14 + p];
    float dfn_p  = (p == 0) ? 1.f : nxt[14 + p - 1];
    float dfn_p1 = (p == 7) ? 1.f : nxt[14 + p];
    float e[8];
    e[0] = cwc_p; e[1] = cwc_p1;
    e[2] = pack_h2(cwn_p - cwc_p, cwn_p1 - cwc_p1);
    e[3] = 0.f;
    e[4] = dfc_p; e[5] = dfc_p1;
    e[6] = pack_h2(dfn_p - dfc_p, dfn_p1 - dfc_p1);
    e[7] = 0.f;
    float* kddst = (fine ? g_kdF + ((size_t)layer * NODES_F + ni) * 64
                         : g_kdC + ((size_t)layer * NODES_C + ni) * 64) + p * 8;
    ((float4*)kddst)[0] = ((const float4*)e)[0];
    ((float4*)kddst)[1] = ((const float4*)e)[1];
}

// ------------------------- exact MLP fallback (rare) ------------------------
__device__ void made_fallback(unsigned need, float out0_self, int l,
                              const float* __restrict__ W0,
                              const float* __restrict__ b0,
                              const float* __restrict__ Wres,
                              const float* __restrict__ bres,
                              const float* __restrict__ Wf,
                              const float* __restrict__ bf,
                              float* p1out, int lane) {
    while (need) {
        int src = __ffs(need) - 1;
        need &= need - 1;
        float x0 = __shfl_sync(0xffffffffu, out0_self, src);
        float h[4];
        #pragma unroll
        for (int jj = 0; jj < 4; jj++) {
            int j = jj * 32 + lane;
            h[jj] = fmaf(x0, W0[(l * HDIM + j) * 2], b0[l * HDIM + j]);
        }
        #pragma unroll 1
        for (int blk = 0; blk < 2; blk++) {
            float v[4], a1[4], a2[4];
            #pragma unroll
            for (int jj = 0; jj < 4; jj++) v[jj] = fmaxf(h[jj], 0.f);
            const float* Wa = Wres + (size_t)((l * 2 + blk) * 2 + 0) * 16384;
            const float* ba = bres + ((l * 2 + blk) * 2 + 0) * 128;
            #pragma unroll
            for (int jj = 0; jj < 4; jj++) a1[jj] = ba[jj * 32 + lane];
            for (int kk = 0; kk < 4; kk++) {
                float vv = v[kk];
                for (int k2 = 0; k2 < 32; k2++) {
                    float vk = __shfl_sync(0xffffffffu, vv, k2);
                    int k = kk * 32 + k2;
                    #pragma unroll
                    for (int jj = 0; jj < 4; jj++)
                        a1[jj] = fmaf(Wa[(jj * 32 + lane) * 128 + k], vk, a1[jj]);
                }
            }
            #pragma unroll
            for (int jj = 0; jj < 4; jj++) a1[jj] = fmaxf(a1[jj], 0.f);
            const float* Wb = Wres + (size_t)((l * 2 + blk) * 2 + 1) * 16384;
            const float* bb = bres + ((l * 2 + blk) * 2 + 1) * 128;
            #pragma unroll
            for (int jj = 0; jj < 4; jj++) a2[jj] = bb[jj * 32 + lane];
            for (int kk = 0; kk < 4; kk++) {
                float vv = a1[kk];
                for (int k2 = 0; k2 < 32; k2++) {
                    float vk = __shfl_sync(0xffffffffu, vv, k2);
                    int k = kk * 32 + k2;
                    #pragma unroll
                    for (int jj = 0; jj < 4; jj++)
                        a2[jj] = fmaf(Wb[(jj * 32 + lane) * 128 + k], vk, a2[jj]);
                }
            }
            #pragma unroll
            for (int jj = 0; jj < 4; jj++) h[jj] += a2[jj];
        }
        float accp = (lane < PMVAL) ? bf[l * (2 * PMVAL) + PMVAL + lane] : 0.f;
        for (int kk = 0; kk < 4; kk++) {
            float hv = h[kk];
            for (int k2 = 0; k2 < 32; k2++) {
                float vk = __shfl_sync(0xffffffffu, hv, k2);
                int k = kk * 32 + k2;
                if (lane < PMVAL)
                    accp = fmaf(Wf[((size_t)l * (2 * PMVAL) + PMVAL + lane) * 128 + k],
                                vk, accp);
            }
        }
        #pragma unroll
        for (int m = 0; m < PMVAL; m++) {
            float pm = __shfl_sync(0xffffffffu, accp, m);
            if (lane == src) p1out[m] = pm;
        }
    }
}

// ------------------------------ fused flow kernel ---------------------------
__global__ void __launch_bounds__(256)
flow_kernel(const float* __restrict__ z0in, const float* __restrict__ xin,
            const float* __restrict__ sigma,
            const float* __restrict__ n1w1, const float* __restrict__ n1b1,
            const float* __restrict__ n1w2, const float* __restrict__ n1b2,
            const float* __restrict__ n2w1, const float* __restrict__ n2b1,
            const float* __restrict__ n2w2, const float* __restrict__ n2b2,
            const float* __restrict__ made_W0, const float* __restrict__ made_b0,
            const float* __restrict__ made_Wres, const float* __restrict__ made_bres,
            const float* __restrict__ made_Wf, const float* __restrict__ made_bf,
            const float* __restrict__ lu_bias, const int* __restrict__ perms,
            float* __restrict__ out) {
    __shared__ float s1w[32], s1b[32], s1o[64], s1ob[2];
    __shared__ float s2w[128], s2b[32], s2o[64], s2ob[2];
    __shared__ float sld;
    __shared__ float sc_cw[NLAYER][9], sc_w[NLAYER][8], sc_ch[NLAYER][9];
    __shared__ float sc_h[NLAYER][8], sc_d[NLAYER][9];
    __shared__ float sc_invW[NLAYER][4], sc_b2[NLAYER][2];
    __shared__ int   sc_perm[NLAYER][2];

    const int tid  = threadIdx.x;
    const int lane = tid & 31;

    if (tid < 32) { s1w[tid] = n1w1[tid]; s1b[tid] = n1b1[tid]; s2b[tid] = n2b1[tid]; }
    if (tid < 64) { s1o[tid] = n1w2[tid]; s2o[tid] = n2w2[tid]; }
    if (tid < 128) s2w[tid] = n2w1[tid];
    if (tid < 2)  { s1ob[tid] = n1b2[tid]; s2ob[tid] = n2b2[tid]; }
    if (tid == 0) sld = g_ldinit;
    for (int i = tid; i < NLAYER * 9; i += 256) {
        sc_cw[i / 9][i % 9] = g_cw0[i];
        sc_ch[i / 9][i % 9] = g_ch0[i];
        sc_d [i / 9][i % 9] = g_d0[i];
    }
    for (int i = tid; i < NLAYER * 8; i += 256) {
        sc_w[i / 8][i % 8] = g_w0[i];
        sc_h[i / 8][i % 8] = g_h0[i];
    }
    for (int i = tid; i < NLAYER * 4; i += 256) sc_invW[i / 4][i % 4] = g_invW[i];
    for (int i = tid; i < NLAYER * 2; i += 256) {
        sc_b2[i / 2][i % 2]   = lu_bias[i];
        sc_perm[i / 2][i % 2] = perms[i];
    }
    __syncthreads();

    const int row = blockIdx.x * 256 + tid;

    // ---- prelude (fused) ----
    float sg = sigma[row];
    float2 zv = ((const float2*)z0in)[row];
    float2 xv = ((const float2*)xin)[row];
    float t0 = s1ob[0], t1 = s1ob[1];
    #pragma unroll
    for (int j = 0; j < 32; j++) {
        float hv = s1w[j] * sg + s1b[j];
        hv = hv * __frcp_rn(1.f + __expf(-hv));
        t0 += s1o[j] * hv;
        t1 += s1o[32 + j] * hv;
    }
    float zc0 = s2ob[0], zc1 = s2ob[1];
    #pragma unroll
    for (int j = 0; j < 32; j++) {
        float hv = s2w[4 * j] * zv.x + s2w[4 * j + 1] * zv.y
                 + s2w[4 * j + 2] * xv.x + s2w[4 * j + 3] * xv.y + s2b[j];
        hv = hv * __frcp_rn(1.f + __expf(-hv));
        zc0 += s2o[j] * hv;
        zc1 += s2o[32 + j] * hv;
    }
    float z0 = zc0 + t0;
    float z1 = zc1 + t1;
    float ld = sld;

    // ---- 16 layers ----
    #pragma unroll 1
    for (int l = 0; l < NLAYER; l++) {
        float out0, ldp0;
        rqs_reg(z0, sc_cw[l], sc_w[l], sc_ch[l], sc_h[l], sc_d[l], out0, ldp0);

        float uf = (out0 + 4.f)  * TINVD_F;
        float uc = (out0 + 16.f) * TINVD_C;
        bool useF = (uf >= 0.f) && (uf < (float)(NODES_F - 1));
        bool useC = !useF && (uc >= 0.f) && (uc < (float)(NODES_C - 1));
        bool inr  = useF || useC;

        float out1 = z1, ldp1 = 0.f;
        if (inr) {
            float u = useF ? uf : uc;
            int i = (int)u;
            float f = u - (float)i;
            size_t nidx = useF ? ((size_t)l * NODES_F + i) : ((size_t)l * NODES_C + i);
            const float* s1p = (useF ? g_s1F : g_s1C) + nidx * 12;
            const float* kdp = (useF ? g_kdF : g_kdC) + nidx * 64;

            // stage 1: lerped ch -> bin k, yk, yk1
            float4 q0 = ((const float4*)s1p)[0];
            float4 q1 = ((const float4*)s1p)[1];
            float4 q2 = ((const float4*)s1p)[2];
            float d01, d23, d45, d6x, dlo, dhi;
            float chL[9];
            chL[0] = -TBV; chL[8] = TBV;
            unpack_h2(q1.w, d01, d23);
            chL[1] = fmaf(f, d01, q0.x);
            chL[2] = fmaf(f, d23, q0.y);
            unpack_h2(q2.x, d45, d6x);
            chL[3] = fmaf(f, d45, q0.z);
            chL[4] = fmaf(f, d6x, q0.w);
            unpack_h2(q2.y, dlo, dhi);
            chL[5] = fmaf(f, dlo, q1.x);
            chL[6] = fmaf(f, dhi, q1.y);
            unpack_h2(q2.z, dlo, dhi);
            chL[7] = fmaf(f, dlo, q1.z);

            bool inside = (z1 >= -TBV) && (z1 <= TBV);
            float yc = fminf(fmaxf(z1, -TBV), TBV);
            int k = 0;
            float yk = chL[0], yk1 = chL[1];
            #pragma unroll
            for (int j = 1; j < NBINS; j++) {
                bool c = yc >= chL[j];
                k   = c ? j : k;
                yk  = c ? chL[j] : yk;
                yk1 = c ? chL[j + 1] : yk1;
            }

            // stage 2: k-indexed cw/d pair with fp16 deltas
            const float4* e = (const float4*)(kdp + k * 8);
            float4 a = e[0];
            float4 b = e[1];
            float dcl, dch_, ddl, ddh;
            unpack_h2(a.z, dcl, dch_);
            unpack_h2(b.z, ddl, ddh);
            float xk  = fmaf(f, dcl,  a.x);
            float xk1 = fmaf(f, dch_, a.y);
            float dk  = fmaf(f, ddl,  b.x);
            float dk1 = fmaf(f, ddh,  b.y);

            float hk = yk1 - yk, wk = xk1 - xk;
            float sk = __fdividef(hk, wk);
            float dy = yc - yk;
            float t2 = dk + dk1 - 2.f * sk;
            float qa = dy * t2 + hk * (sk - dk);
            float qb = hk * dk - dy * t2;
            float qc = -sk * dy;
            float disc = fmaxf(qb * qb - 4.f * qa * qc, 0.f);
            float theta = __fdividef(2.f * qc, -qb - sqrtf(disc));
            float xo = theta * wk + xk;
            float om = 1.f - theta;
            float denom = sk + t2 * theta * om;
            float dnum = sk * sk * (dk1 * theta * theta + 2.f * sk * theta * om + dk * om * om);
            float ldf = __logf(__fdividef(dnum, denom * denom));
            out1 = inside ? xo : z1;
            ldp1 = inside ? -ldf : 0.f;
        }
        unsigned need = __ballot_sync(0xffffffffu, !inr);
        if (need) {
            float p1[PMVAL];
            made_fallback(need, out0, l, made_W0, made_b0, made_Wres, made_bres,
                          made_Wf, made_bf, p1, lane);
            if (!inr) {
                float cw9[9], ch9[9], dd9[9];
                knots_from_p1(p1, cw9, ch9, dd9);
                rqs_knots(z1, cw9, ch9, dd9, out1, ldp1);
            }
        }

        ld += ldp0 + ldp1;
        float v0 = out0 - sc_b2[l][0];
        float v1 = out1 - sc_b2[l][1];
        float zz0 = sc_invW[l][0] * v0 + sc_invW[l][1] * v1;
        float zz1 = sc_invW[l][2] * v0 + sc_invW[l][3] * v1;
        z0 = sc_perm[l][0] ? zz1 : zz0;
        z1 = sc_perm[l][1] ? zz1 : zz0;
    }

    ((float2*)out)[row] = make_float2(z0, z1);
    out[2 * BATCH + row] = ld;
}

// ------------------------------ launcher -----------------------------------
extern "C" void kernel_launch(void* const* d_in, const int* in_sizes, int n_in,
                              void* d_out, int out_size) {
    const float* z0      = (const float*)d_in[0];
    const float* x       = (const float*)d_in[1];
    const float* sigma   = (const float*)d_in[2];
    const float* n1_w1   = (const float*)d_in[3];
    const float* n1_b1   = (const float*)d_in[4];
    const float* n1_w2   = (const float*)d_in[5];
    const float* n1_b2   = (const float*)d_in[6];
    const float* n2_w1   = (const float*)d_in[7];
    const float* n2_b1   = (const float*)d_in[8];
    const float* n2_w2   = (const float*)d_in[9];
    const float* n2_b2   = (const float*)d_in[10];
    const float* made_W0 = (const float*)d_in[11];
    const float* made_b0 = (const float*)d_in[12];
    const float* made_Wres = (const float*)d_in[13];
    const float* made_bres = (const float*)d_in[14];
    const float* made_Wf   = (const float*)d_in[15];
    const float* made_bf   = (const float*)d_in[16];
    const float* lu_lower  = (const float*)d_in[17];
    const float* lu_upper  = (const float*)d_in[18];
    const float* lu_diag   = (const float*)d_in[19];
    const float* lu_bias   = (const float*)d_in[20];
    const int*   perms     = (const int*)d_in[21];
    float* out = (float*)d_out;

    cudaFuncSetAttribute(table_build_kernel,
                         cudaFuncAttributeMaxDynamicSharedMemorySize, DYN_SMEM);

    build_wimg_kernel<<<2048, 256>>>(made_Wres, made_Wf);
    setup_kernel<<<1, 32>>>(made_bf, lu_lower, lu_upper, lu_diag);
    table_build_kernel<<<NLAYER * BLKS_PER_LAYER, 256, DYN_SMEM>>>(
        made_W0, made_b0, made_bres, made_bf);
    pack_kernel<<<(NLAYER * NODES_T * 8 + 255) / 256, 256>>>();
    flow_kernel<<<BATCH / 256, 256>>>(
        z0, x, sigma, n1_w1, n1_b1, n1_w2, n1_b2,
        n2_w1, n2_b1, n2_w2, n2_b2,
        made_W0, made_b0, made_Wres, made_bres, made_Wf, made_bf,
        lu_bias, perms, out);
    (void)in_sizes; (void)n_in; (void)out_size;
}

// round 15
// speedup vs baseline: 1.5128x; 1.5128x over previous
#include <cuda_runtime.h>
#include <cuda_bf16.h>
#include <cuda_fp16.h>
#include <math.h>
#include <stdint.h>
#include <string.h>

// ---------------------------------------------------------------------------
// NeuralSplineFlow forward — bin-directed derived-knot table (R13) with a
// one-wave table build at FULL R13 precision (R15): fine grid shrunk to
// [-3.25, 3.25] at delta 1/128 (out0 from the inside-spline path is bounded
// in [-3,3]; beyond that only rare passthrough tails, served by the coarse
// table). 962 total nodes -> 8 blocks/layer -> 128 blocks = ONE wave.
// Flow kernel identical to R13 apart from the fine-table origin constant.
// ---------------------------------------------------------------------------

#define BATCH   262144
#define NLAYER  16
#define HDIM    128
#define NBINS   8
#define PMVAL   23
#define TBV     3.0f
#define MINWV   0.001f
#define MINDV   0.001f
#define LUEPS   0.001f
#define INV_SQH 0.08838834764831843f   // 1/sqrt(128)

// dual-resolution table
#define NODES_F 833                    // [-3.25, 3.25], delta 1/128
#define NODES_C 129                    // [-16,16], delta 1/4
#define NODES_T (NODES_F + NODES_C)    // 962
#define BLKS_PER_LAYER 8               // ceil(962/128) -> 128 blocks = 1 wave
#define TLO_F    (-3.25f)              // exact binary; 3.25*128 = 416
#define TINVD_F  128.0f
#define TDELTA_F 0.0078125f
#define TINVD_C  4.0f
#define TDELTA_C 0.25f

// SMEM geometry for the table-build (mma) kernel
#define KSTRIDE   136
#define ROWB      (KSTRIDE * 2)
#define ACT_BYTES (HDIM * ROWB)          // 34816
#define WMAT_ELEMS (HDIM * KSTRIDE)
#define WSLOT_BYTES (2 * ACT_BYTES)      // 69632
#define WF_STRIDE 40
#define WF_HALF   (HDIM * WF_STRIDE)
#define WF_BYTES  (2 * WF_HALF * 2)

#define OFF_ACTHI 0
#define OFF_ACTLO 34816
#define OFF_SLOT0 69632
#define OFF_SLOT1 139264
#define OFF_P1    139264
#define DYN_SMEM  208896

// ----------------------------- device scratch ------------------------------
__device__ __align__(16) uint16_t g_Wimg[NLAYER * 4 * 2 * WMAT_ELEMS];
__device__ __align__(16) uint16_t g_Wfimg[NLAYER * 2 * WF_HALF];
__device__ __align__(16) float g_ktF[NLAYER * NODES_F * 24];
__device__ __align__(16) float g_ktC[NLAYER * NODES_C * 24];
__device__ __align__(16) float g_s1F[NLAYER * NODES_F * 12];
__device__ __align__(16) float g_s1C[NLAYER * NODES_C * 12];
__device__ __align__(16) float g_kdF[NLAYER * NODES_F * 64];
__device__ __align__(16) float g_kdC[NLAYER * NODES_C * 64];
__device__ float g_cw0[NLAYER * 9];
__device__ float g_w0[NLAYER * 8];
__device__ float g_ch0[NLAYER * 9];
__device__ float g_h0[NLAYER * 8];
__device__ float g_d0[NLAYER * 9];
__device__ float g_invW[NLAYER * 4];
__device__ float g_ldinit;

// ----------------------------- PTX helpers ---------------------------------
__device__ __forceinline__ uint32_t smem_u32(const void* p) {
    uint32_t a;
    asm("{ .reg .u64 t; cvta.to.shared.u64 t, %1; cvt.u32.u64 %0, t; }"
        : "=r"(a) : "l"(p));
    return a;
}
__device__ __forceinline__ void ldmA4(uint32_t a[4], uint32_t addr) {
    asm volatile("ldmatrix.sync.aligned.m8n8.x4.shared.b16 {%0,%1,%2,%3}, [%4];"
        : "=r"(a[0]), "=r"(a[1]), "=r"(a[2]), "=r"(a[3]) : "r"(addr));
}
__device__ __forceinline__ void ldmB4t(uint32_t b[4], uint32_t addr) {
    asm volatile("ldmatrix.sync.aligned.m8n8.x4.trans.shared.b16 {%0,%1,%2,%3}, [%4];"
        : "=r"(b[0]), "=r"(b[1]), "=r"(b[2]), "=r"(b[3]) : "r"(addr));
}
__device__ __forceinline__ void mmabf(float d[4], const uint32_t a[4],
                                      uint32_t b0, uint32_t b1) {
    asm volatile("mma.sync.aligned.m16n8k16.row.col.f32.bf16.bf16.f32 "
        "{%0,%1,%2,%3}, {%4,%5,%6,%7}, {%8,%9}, {%0,%1,%2,%3};"
        : "+f"(d[0]), "+f"(d[1]), "+f"(d[2]), "+f"(d[3])
        : "r"(a[0]), "r"(a[1]), "r"(a[2]), "r"(a[3]), "r"(b0), "r"(b1));
}
__device__ __forceinline__ void cpasync16(uint32_t dst, const void* src) {
    asm volatile("cp.async.cg.shared.global [%0], [%1], 16;"
                 :: "r"(dst), "l"(src));
}
#define CP_COMMIT() asm volatile("cp.async.commit_group;" ::: "memory")
#define CP_WAIT0()  asm volatile("cp.async.wait_group 0;" ::: "memory")

__device__ __forceinline__ float pack_h2(float a, float b) {
    __half2 h = __floats2half2_rn(a, b);
    uint32_t u;
    memcpy(&u, &h, 4);
    return __uint_as_float(u);
}
__device__ __forceinline__ void unpack_h2(float p, float& lo, float& hi) {
    uint32_t u = __float_as_uint(p);
    __half2 h;
    memcpy(&h, &u, 4);
    lo = __low2float(h);
    hi = __high2float(h);
}

// ----------------------------- math helpers --------------------------------
__device__ __forceinline__ float softplusf(float x) {
    return fmaxf(x, 0.f) + log1pf(expf(-fabsf(x)));
}
__device__ __forceinline__ float softplus_fast(float x) {
    return fmaxf(x, 0.f) + __logf(1.f + __expf(-fabsf(x)));
}

__device__ void build_params(const float* uw, const float* uh, const float* ud,
                             float* cw, float* w, float* ch, float* hh, float* dd) {
    {
        float mx = uw[0];
        #pragma unroll
        for (int k = 1; k < NBINS; k++) mx = fmaxf(mx, uw[k]);
        float e[NBINS]; float s = 0.f;
        #pragma unroll
        for (int k = 0; k < NBINS; k++) { e[k] = expf(uw[k] - mx); s += e[k]; }
        float inv = 1.f / s;
        cw[0] = -TBV; float cum = 0.f;
        #pragma unroll
        for (int k = 0; k < NBINS; k++) {
            float wk = MINWV + (1.f - MINWV * NBINS) * e[k] * inv;
            cum += wk;
            cw[k + 1] = 2.f * TBV * cum - TBV;
        }
        cw[NBINS] = TBV;
        #pragma unroll
        for (int k = 0; k < NBINS; k++) w[k] = cw[k + 1] - cw[k];
    }
    {
        float mx = uh[0];
        #pragma unroll
        for (int k = 1; k < NBINS; k++) mx = fmaxf(mx, uh[k]);
        float e[NBINS]; float s = 0.f;
        #pragma unroll
        for (int k = 0; k < NBINS; k++) { e[k] = expf(uh[k] - mx); s += e[k]; }
        float inv = 1.f / s;
        ch[0] = -TBV; float cum = 0.f;
        #pragma unroll
        for (int k = 0; k < NBINS; k++) {
            float hk = MINWV + (1.f - MINWV * NBINS) * e[k] * inv;
            cum += hk;
            ch[k + 1] = 2.f * TBV * cum - TBV;
        }
        ch[NBINS] = TBV;
        #pragma unroll
        for (int k = 0; k < NBINS; k++) hh[k] = ch[k + 1] - ch[k];
    }
    dd[0] = 1.0f;
    #pragma unroll
    for (int k = 0; k < 7; k++) dd[k + 1] = MINDV + softplusf(ud[k]);
    dd[NBINS] = 1.0f;
}

__device__ __forceinline__ void rqs_reg(float y, const float cw[9], const float w[8],
                                        const float ch[9], const float hh[8],
                                        const float dd[9], float& xout, float& ldout) {
    bool inside = (y >= -TBV) && (y <= TBV);
    float yc = fminf(fmaxf(y, -TBV), TBV);
    float yk = ch[0], hk = hh[0], xk = cw[0], wk = w[0], dk = dd[0], dk1 = dd[1];
    #pragma unroll
    for (int k = 1; k < NBINS; k++) {
        bool c = yc >= ch[k];
        yk  = c ? ch[k]     : yk;
        hk  = c ? hh[k]     : hk;
        xk  = c ? cw[k]     : xk;
        wk  = c ? w[k]      : wk;
        dk  = c ? dd[k]     : dk;
        dk1 = c ? dd[k + 1] : dk1;
    }
    float sk = __fdividef(hk, wk);
    float dy = yc - yk;
    float t2 = dk + dk1 - 2.f * sk;
    float qa = dy * t2 + hk * (sk - dk);
    float qb = hk * dk - dy * t2;
    float qc = -sk * dy;
    float disc = fmaxf(qb * qb - 4.f * qa * qc, 0.f);
    float theta = __fdividef(2.f * qc, -qb - sqrtf(disc));
    float xo = theta * wk + xk;
    float om = 1.f - theta;
    float denom = sk + t2 * theta * om;
    float dnum = sk * sk * (dk1 * theta * theta + 2.f * sk * theta * om + dk * om * om);
    float ldf = __logf(__fdividef(dnum, denom * denom));
    xout  = inside ? xo : y;
    ldout = inside ? -ldf : 0.f;
}

__device__ __forceinline__ void rqs_knots(float y, const float cw[9], const float ch[9],
                                          const float dd[9], float& xout, float& ldout) {
    bool inside = (y >= -TBV) && (y <= TBV);
    float yc = fminf(fmaxf(y, -TBV), TBV);
    float yk = ch[0], yk1 = ch[1], xk = cw[0], xk1 = cw[1], dk = dd[0], dk1 = dd[1];
    #pragma unroll
    for (int k = 1; k < NBINS; k++) {
        bool c = yc >= ch[k];
        yk  = c ? ch[k]     : yk;
        yk1 = c ? ch[k + 1] : yk1;
        xk  = c ? cw[k]     : xk;
        xk1 = c ? cw[k + 1] : xk1;
        dk  = c ? dd[k]     : dk;
        dk1 = c ? dd[k + 1] : dk1;
    }
    float hk = yk1 - yk, wk = xk1 - xk;
    float sk = __fdividef(hk, wk);
    float dy = yc - yk;
    float t2 = dk + dk1 - 2.f * sk;
    float qa = dy * t2 + hk * (sk - dk);
    float qb = hk * dk - dy * t2;
    float qc = -sk * dy;
    float disc = fmaxf(qb * qb - 4.f * qa * qc, 0.f);
    float theta = __fdividef(2.f * qc, -qb - sqrtf(disc));
    float xo = theta * wk + xk;
    float om = 1.f - theta;
    float denom = sk + t2 * theta * om;
    float dnum = sk * sk * (dk1 * theta * theta + 2.f * sk * theta * om + dk * om * om);
    float ldf = __logf(__fdividef(dnum, denom * denom));
    xout  = inside ? xo : y;
    ldout = inside ? -ldf : 0.f;
}

__device__ __forceinline__ void knots_from_p1(const float* p1, float cw[9],
                                              float ch[9], float dd[9]) {
    float uw[8], uh[8];
    #pragma unroll
    for (int k = 0; k < 8; k++) { uw[k] = p1[k] * INV_SQH; uh[k] = p1[8 + k] * INV_SQH; }
    float mw = uw[0], mh = uh[0];
    #pragma unroll
    for (int k = 1; k < 8; k++) { mw = fmaxf(mw, uw[k]); mh = fmaxf(mh, uh[k]); }
    float ew[8], eh[8], sw = 0.f, sh = 0.f;
    #pragma unroll
    for (int k = 0; k < 8; k++) {
        ew[k] = __expf(uw[k] - mw); sw += ew[k];
        eh[k] = __expf(uh[k] - mh); sh += eh[k];
    }
    float iw = __fdividef(1.f - MINWV * NBINS, sw);
    float ih = __fdividef(1.f - MINWV * NBINS, sh);
    cw[0] = -TBV; ch[0] = -TBV;
    float cumw = 0.f, cumh = 0.f;
    #pragma unroll
    for (int k = 0; k < 7; k++) {
        cumw += MINWV + iw * ew[k];
        cumh += MINWV + ih * eh[k];
        cw[k + 1] = fmaf(2.f * TBV, cumw, -TBV);
        ch[k + 1] = fmaf(2.f * TBV, cumh, -TBV);
    }
    cw[8] = TBV; ch[8] = TBV;
    dd[0] = 1.f; dd[8] = 1.f;
    #pragma unroll
    for (int k = 0; k < 7; k++) dd[k + 1] = MINDV + softplus_fast(p1[16 + k]);
}

__device__ __forceinline__ void split2(float a, float b, uint32_t& hi, uint32_t& lo) {
    __nv_bfloat16 ah = __float2bfloat16(a), bh = __float2bfloat16(b);
    __nv_bfloat16 al = __float2bfloat16(a - __bfloat162float(ah));
    __nv_bfloat16 bl = __float2bfloat16(b - __bfloat162float(bh));
    hi = (uint32_t)__bfloat16_as_ushort(ah) | ((uint32_t)__bfloat16_as_ushort(bh) << 16);
    lo = (uint32_t)__bfloat16_as_ushort(al) | ((uint32_t)__bfloat16_as_ushort(bl) << 16);
}

// ------------------------------ setup kernels ------------------------------
// n-fastest => coalesced STORES (scattered reads hit L2).
__global__ void build_wimg_kernel(const float* __restrict__ Wres,
                                  const float* __restrict__ Wf) {
    const int total1 = NLAYER * 4 * HDIM * KSTRIDE;
    for (int t = blockIdx.x * blockDim.x + threadIdx.x; t < total1;
         t += gridDim.x * blockDim.x) {
        int n  = t % KSTRIDE;
        int k  = (t / KSTRIDE) % HDIM;
        int mg = t / (KSTRIDE * HDIM);
        float v = (n < HDIM) ? Wres[mg * 16384 + n * HDIM + k] : 0.f;
        __nv_bfloat16 h = __float2bfloat16(v);
        __nv_bfloat16 l = __float2bfloat16(v - __bfloat162float(h));
        int base = (mg * 2) * WMAT_ELEMS + k * KSTRIDE + n;
        g_Wimg[base]              = __bfloat16_as_ushort(h);
        g_Wimg[base + WMAT_ELEMS] = __bfloat16_as_ushort(l);
    }
    const int total2 = NLAYER * HDIM * WF_STRIDE;
    for (int t = blockIdx.x * blockDim.x + threadIdx.x; t < total2;
         t += gridDim.x * blockDim.x) {
        int n  = t % WF_STRIDE;
        int k  = (t / WF_STRIDE) % HDIM;
        int ly = t / (WF_STRIDE * HDIM);
        float v = (n < PMVAL) ? Wf[(ly * (2 * PMVAL) + PMVAL + n) * HDIM + k] : 0.f;
        __nv_bfloat16 h = __float2bfloat16(v);
        __nv_bfloat16 l = __float2bfloat16(v - __bfloat162float(h));
        int base = (ly * 2) * WF_HALF + k * WF_STRIDE + n;
        g_Wfimg[base]           = __bfloat16_as_ushort(h);
        g_Wfimg[base + WF_HALF] = __bfloat16_as_ushort(l);
    }
}

__global__ void setup_kernel(const float* __restrict__ made_bf,
                             const float* __restrict__ lu_lower,
                             const float* __restrict__ lu_upper,
                             const float* __restrict__ lu_diag) {
    __shared__ float sldl[NLAYER];
    int i = threadIdx.x;
    if (i < NLAYER) {
        const float* bfL = made_bf + i * (2 * PMVAL);
        float uw[8], uh[8], ud[7];
        #pragma unroll
        for (int k = 0; k < 8; k++) { uw[k] = bfL[k] * INV_SQH; uh[k] = bfL[8 + k] * INV_SQH; }
        #pragma unroll
        for (int k = 0; k < 7; k++) ud[k] = bfL[16 + k];
        build_params(uw, uh, ud, g_cw0 + 9 * i, g_w0 + 8 * i,
                     g_ch0 + 9 * i, g_h0 + 8 * i, g_d0 + 9 * i);
        float l = lu_lower[i], u = lu_upper[i];
        float d0 = softplusf(lu_diag[2 * i]) + LUEPS;
        float d1 = softplusf(lu_diag[2 * i + 1]) + LUEPS;
        float invdet = 1.f / (d0 * d1);
        g_invW[4 * i + 0] = (l * u + d1) * invdet;
        g_invW[4 * i + 1] = -u * invdet;
        g_invW[4 * i + 2] = -l * d0 * invdet;
        g_invW[4 * i + 3] = d0 * invdet;
        sldl[i] = logf(d0) + logf(d1);
    }
    __syncthreads();
    if (i == 0) {
        float s = 0.f;
        for (int j = 0; j < NLAYER; j++) s += sldl[j];
        g_ldinit = -s;
    }
}

// ------------------------- table-build (mma) kernel -------------------------
__device__ __forceinline__ void prefetch_w(uint32_t dst_u, const uint16_t* gsrc,
                                           int chunks, int tid) {
    const char* s = (const char*)gsrc;
    for (int i = tid; i < chunks; i += 256)
        cpasync16(dst_u + i * 16, s + i * 16);
    CP_COMMIT();
}

__global__ void __launch_bounds__(256, 1)
table_build_kernel(const float* __restrict__ made_W0,
                   const float* __restrict__ made_b0,
                   const float* __restrict__ made_bres,
                   const float* __restrict__ made_bf) {
    extern __shared__ char dynsm[];
    __shared__ float s_bias[4][HDIM];
    __shared__ float s_out0[HDIM];
    __shared__ float s_w0col[HDIM], s_b0[HDIM];

    const int layer = blockIdx.x / BLKS_PER_LAYER;
    const int tile  = blockIdx.x % BLKS_PER_LAYER;
    const int tid   = threadIdx.x;
    const int lane  = tid & 31;
    const int w     = tid >> 5;

    const uint32_t base_u  = smem_u32(dynsm);
    const uint32_t actHi_u = base_u + OFF_ACTHI;
    const uint32_t slot_u[2] = { base_u + OFF_SLOT0, base_u + OFF_SLOT1 };

    prefetch_w(slot_u[0], g_Wimg + (size_t)(layer * 4) * (2 * WMAT_ELEMS),
               WSLOT_BYTES / 16, tid);

    if (tid < HDIM) {
        s_w0col[tid] = made_W0[(layer * HDIM + tid) * 2];
        s_b0[tid]    = made_b0[layer * HDIM + tid];
        int node = tile * HDIM + tid;
        float x = (node < NODES_F)
                ? (TLO_F + (float)node * TDELTA_F)
                : (-16.f + (float)(node - NODES_F) * TDELTA_C);
        s_out0[tid] = x;
    }
    for (int i = tid; i < 4 * HDIM; i += 256)
        s_bias[i >> 7][i & 127] = made_bres[layer * 4 * HDIM + i];
    __syncthreads();

    const int r0 = w * 16 + (lane >> 2);
    const int r1 = r0 + 8;
    const int cB = (lane & 3) * 2;
    const uint32_t o0 = (uint32_t)r0 * ROWB + cB * 2;
    const uint32_t o1 = (uint32_t)r1 * ROWB + cB * 2;

    float H[64];
    {
        float oa = s_out0[r0], ob = s_out0[r1];
        #pragma unroll
        for (int t = 0; t < 16; t++) {
            int c = t * 8 + cB;
            float2 wc = *(const float2*)&s_w0col[c];
            float2 bc = *(const float2*)&s_b0[c];
            float h0 = fmaf(oa, wc.x, bc.x), h1 = fmaf(oa, wc.y, bc.y);
            float h2 = fmaf(ob, wc.x, bc.x), h3 = fmaf(ob, wc.y, bc.y);
            H[t * 4] = h0; H[t * 4 + 1] = h1; H[t * 4 + 2] = h2; H[t * 4 + 3] = h3;
            uint32_t hi0, lo0, hi1, lo1;
            split2(fmaxf(h0, 0.f), fmaxf(h1, 0.f), hi0, lo0);
            split2(fmaxf(h2, 0.f), fmaxf(h3, 0.f), hi1, lo1);
            *(uint32_t*)(dynsm + OFF_ACTHI + o0 + t * 16) = hi0;
            *(uint32_t*)(dynsm + OFF_ACTHI + o1 + t * 16) = hi1;
            *(uint32_t*)(dynsm + OFF_ACTLO + o0 + t * 16) = lo0;
            *(uint32_t*)(dynsm + OFF_ACTLO + o1 + t * 16) = lo1;
        }
    }
    CP_WAIT0();
    __syncthreads();

    const uint32_t aHiBase = actHi_u + (uint32_t)(w * 16 + (lane & 15)) * ROWB
                             + ((lane >> 4) * 16);
    const uint32_t aLoBase = aHiBase + ACT_BYTES;
    const uint32_t bOff    = (uint32_t)(lane & 15) * ROWB + ((lane >> 4) * 16);
    const uint32_t wfOff   = (uint32_t)(lane & 15) * (WF_STRIDE * 2) + ((lane >> 4) * 16);

    #pragma unroll 1
    for (int g = 0; g < 4; g++) {
        if (g < 3)
            prefetch_w(slot_u[(g + 1) & 1],
                       g_Wimg + (size_t)(layer * 4 + g + 1) * (2 * WMAT_ELEMS),
                       WSLOT_BYTES / 16, tid);
        else
            prefetch_w(slot_u[0], g_Wfimg + (size_t)layer * (2 * WF_HALF),
                       WF_BYTES / 16, tid);

        __syncwarp();
        uint32_t Ah[8][4], Al[8][4];
        #pragma unroll
        for (int kc = 0; kc < 8; kc++) {
            ldmA4(Ah[kc], aHiBase + kc * 32);
            ldmA4(Al[kc], aLoBase + kc * 32);
        }
        const uint32_t wbase = slot_u[g & 1] + bOff;

        #pragma unroll
        for (int tp = 0; tp < 8; tp++) {
            float D0[4] = {0.f, 0.f, 0.f, 0.f};
            float D1[4] = {0.f, 0.f, 0.f, 0.f};
            #pragma unroll
            for (int kc = 0; kc < 8; kc++) {
                uint32_t bh[4], bl[4];
                ldmB4t(bh, wbase + kc * (16 * ROWB) + tp * 32);
                ldmB4t(bl, wbase + ACT_BYTES + kc * (16 * ROWB) + tp * 32);
                mmabf(D0, Ah[kc], bh[0], bh[1]);
                mmabf(D0, Al[kc], bh[0], bh[1]);
                mmabf(D0, Ah[kc], bl[0], bl[1]);
                mmabf(D1, Ah[kc], bh[2], bh[3]);
                mmabf(D1, Al[kc], bh[2], bh[3]);
                mmabf(D1, Ah[kc], bl[2], bl[3]);
            }
            #pragma unroll
            for (int q = 0; q < 2; q++) {
                const int t = tp * 2 + q;
                float* D = q ? D1 : D0;
                float2 bb = *(const float2*)&s_bias[g][t * 8 + cB];
                float v0, v1, v2, v3;
                if ((g & 1) == 0) {
                    v0 = fmaxf(D[0] + bb.x, 0.f);
                    v1 = fmaxf(D[1] + bb.y, 0.f);
                    v2 = fmaxf(D[2] + bb.x, 0.f);
                    v3 = fmaxf(D[3] + bb.y, 0.f);
                } else {
                    float n0 = H[t * 4]     + D[0] + bb.x;
                    float n1 = H[t * 4 + 1] + D[1] + bb.y;
                    float n2 = H[t * 4 + 2] + D[2] + bb.x;
                    float n3 = H[t * 4 + 3] + D[3] + bb.y;
                    H[t * 4] = n0; H[t * 4 + 1] = n1;
                    H[t * 4 + 2] = n2; H[t * 4 + 3] = n3;
                    if (g == 3) { v0 = n0; v1 = n1; v2 = n2; v3 = n3; }
                    else { v0 = fmaxf(n0, 0.f); v1 = fmaxf(n1, 0.f);
                           v2 = fmaxf(n2, 0.f); v3 = fmaxf(n3, 0.f); }
                }
                uint32_t hi0, lo0, hi1, lo1;
                split2(v0, v1, hi0, lo0);
                split2(v2, v3, hi1, lo1);
                *(uint32_t*)(dynsm + OFF_ACTHI + o0 + t * 16) = hi0;
                *(uint32_t*)(dynsm + OFF_ACTHI + o1 + t * 16) = hi1;
                *(uint32_t*)(dynsm + OFF_ACTLO + o0 + t * 16) = lo0;
                *(uint32_t*)(dynsm + OFF_ACTLO + o1 + t * 16) = lo1;
            }
        }
        CP_WAIT0();
        __syncthreads();
    }

    // Wf GEMM
    {
        __syncwarp();
        uint32_t Ah[8][4], Al[8][4];
        #pragma unroll
        for (int kc = 0; kc < 8; kc++) {
            ldmA4(Ah[kc], aHiBase + kc * 32);
            ldmA4(Al[kc], aLoBase + kc * 32);
        }
        const uint32_t wfb = slot_u[0] + wfOff;
        float* p1 = (float*)(dynsm + OFF_P1);
        #pragma unroll
        for (int tp = 0; tp < 2; tp++) {
            float D0[4] = {0.f, 0.f, 0.f, 0.f};
            float D1[4] = {0.f, 0.f, 0.f, 0.f};
            #pragma unroll
            for (int kc = 0; kc < 8; kc++) {
                uint32_t bh[4], bl[4];
                ldmB4t(bh, wfb + kc * (16 * WF_STRIDE * 2) + tp * 32);
                ldmB4t(bl, wfb + 2 * WF_HALF + kc * (16 * WF_STRIDE * 2) + tp * 32);
                mmabf(D0, Ah[kc], bh[0], bh[1]);
                mmabf(D0, Al[kc], bh[0], bh[1]);
                mmabf(D0, Ah[kc], bl[0], bl[1]);
                mmabf(D1, Ah[kc], bh[2], bh[3]);
                mmabf(D1, Al[kc], bh[2], bh[3]);
                mmabf(D1, Ah[kc], bl[2], bl[3]);
            }
            int c0 = tp * 16 + cB;
            p1[r0 * 26 + c0] = D0[0]; p1[r0 * 26 + c0 + 1] = D0[1];
            p1[r1 * 26 + c0] = D0[2]; p1[r1 * 26 + c0 + 1] = D0[3];
            if (tp == 0) {
                p1[r0 * 26 + c0 + 8] = D1[0]; p1[r0 * 26 + c0 + 9] = D1[1];
                p1[r1 * 26 + c0 + 8] = D1[2]; p1[r1 * 26 + c0 + 9] = D1[3];
            }
        }
    }
    __syncthreads();

    if (tid < HDIM) {
        int node = tile * HDIM + tid;
        if (node < NODES_T) {
            const float* p1r = (const float*)(dynsm + OFF_P1) + tid * 26;
            const float* bf1 = made_bf + layer * (2 * PMVAL) + PMVAL;
            float uw[8], uh[8], ud[7];
            #pragma unroll
            for (int k = 0; k < 8; k++) {
                uw[k] = (p1r[k]     + bf1[k])     * INV_SQH;
                uh[k] = (p1r[8 + k] + bf1[8 + k]) * INV_SQH;
            }
            #pragma unroll
            for (int k = 0; k < 7; k++) ud[k] = p1r[16 + k] + bf1[16 + k];
            float cw[9], ww[8], chh[9], hh2[8], dd[9];
            build_params(uw, uh, ud, cw, ww, chh, hh2, dd);
            float* row = (node < NODES_F)
                ? g_ktF + ((size_t)layer * NODES_F + node) * 24
                : g_ktC + ((size_t)layer * NODES_C + (node - NODES_F)) * 24;
            #pragma unroll
            for (int k = 0; k < 7; k++) {
                row[k]      = cw[k + 1];
                row[7 + k]  = chh[k + 1];
                row[14 + k] = dd[k + 1];
            }
            row[21] = 0.f; row[22] = 0.f; row[23] = 0.f;
        }
    }
}

// pack: 8 threads per node; thread p writes KD entry p, p==0 also writes S1.
__global__ void pack_kernel() {
    int t = blockIdx.x * blockDim.x + threadIdx.x;
    int nodeIdx = t >> 3;
    int p = t & 7;
    if (nodeIdx >= NLAYER * NODES_T) return;
    int layer = nodeIdx / NODES_T;
    int node  = nodeIdx % NODES_T;
    bool fine = (node < NODES_F);
    int ni = fine ? node : node - NODES_F;
    int nn = fine ? min(ni + 1, NODES_F - 1) : min(ni + 1, NODES_C - 1);
    const float* cur = fine ? g_ktF + ((size_t)layer * NODES_F + ni) * 24
                            : g_ktC + ((size_t)layer * NODES_C + ni) * 24;
    const float* nxt = fine ? g_ktF + ((size_t)layer * NODES_F + nn) * 24
                            : g_ktC + ((size_t)layer * NODES_C + nn) * 24;

    if (p == 0) {
        float s1[12];
        #pragma unroll
        for (int k = 0; k < 7; k++) s1[k] = cur[7 + k];
        float dch[7];
        #pragma unroll
        for (int k = 0; k < 7; k++) dch[k] = nxt[7 + k] - cur[7 + k];
        s1[7]  = pack_h2(dch[0], dch[1]);
        s1[8]  = pack_h2(dch[2], dch[3]);
        s1[9]  = pack_h2(dch[4], dch[5]);
        s1[10] = pack_h2(dch[6], 0.f);
        s1[11] = 0.f;
        float* s1dst = fine ? g_s1F + ((size_t)layer * NODES_F + ni) * 12
                            : g_s1C + ((size_t)layer * NODES_C + ni) * 12;
        #pragma unroll
        for (int q = 0; q < 3; q++)
            ((float4*)s1dst)[q] = ((const float4*)s1)[q];
    }

    float cwc_p  = (p == 0) ? -TBV : cur[p - 1];
    float cwc_p1 = (p == 7) ?  TBV : cur[p];
    float cwn_p  = (p == 0) ? -TBV : nxt[p - 1];
    float cwn_p1 = (p == 7) ?  TBV : nxt[p];
    float dfc_p  = (p == 0) ? 1.f : cur[14 + p - 1];
    float dfc_p1 = (p == 7) ? 1.f : cur[14 + p];
    float dfn_p  = (p == 0) ? 1.f : nxt[14 + p - 1];
    float dfn_p1 = (p == 7) ? 1.f : nxt[14 + p];
    float e[8];
    e[0] = cwc_p; e[1] = cwc_p1;
    e[2] = pack_h2(cwn_p - cwc_p, cwn_p1 - cwc_p1);
    e[3] = 0.f;
    e[4] = dfc_p; e[5] = dfc_p1;
    e[6] = pack_h2(dfn_p - dfc_p, dfn_p1 - dfc_p1);
    e[7] = 0.f;
    float* kddst = (fine ? g_kdF + ((size_t)layer * NODES_F + ni) * 64
                         : g_kdC + ((size_t)layer * NODES_C + ni) * 64) + p * 8;
    ((float4*)kddst)[0] = ((const float4*)e)[0];
    ((float4*)kddst)[1] = ((const float4*)e)[1];
}

// ------------------------- exact MLP fallback (rare) ------------------------
__device__ void made_fallback(unsigned need, float out0_self, int l,
                              const float* __restrict__ W0,
                              const float* __restrict__ b0,
                              const float* __restrict__ Wres,
                              const float* __restrict__ bres,
                              const float* __restrict__ Wf,
                              const float* __restrict__ bf,
                              float* p1out, int lane) {
    while (need) {
        int src = __ffs(need) - 1;
        need &= need - 1;
        float x0 = __shfl_sync(0xffffffffu, out0_self, src);
        float h[4];
        #pragma unroll
        for (int jj = 0; jj < 4; jj++) {
            int j = jj * 32 + lane;
            h[jj] = fmaf(x0, W0[(l * HDIM + j) * 2], b0[l * HDIM + j]);
        }
        #pragma unroll 1
        for (int blk = 0; blk < 2; blk++) {
            float v[4], a1[4], a2[4];
            #pragma unroll
            for (int jj = 0; jj < 4; jj++) v[jj] = fmaxf(h[jj], 0.f);
            const float* Wa = Wres + (size_t)((l * 2 + blk) * 2 + 0) * 16384;
            const float* ba = bres + ((l * 2 + blk) * 2 + 0) * 128;
            #pragma unroll
            for (int jj = 0; jj < 4; jj++) a1[jj] = ba[jj * 32 + lane];
            for (int kk = 0; kk < 4; kk++) {
                float vv = v[kk];
                for (int k2 = 0; k2 < 32; k2++) {
                    float vk = __shfl_sync(0xffffffffu, vv, k2);
                    int k = kk * 32 + k2;
                    #pragma unroll
                    for (int jj = 0; jj < 4; jj++)
                        a1[jj] = fmaf(Wa[(jj * 32 + lane) * 128 + k], vk, a1[jj]);
                }
            }
            #pragma unroll
            for (int jj = 0; jj < 4; jj++) a1[jj] = fmaxf(a1[jj], 0.f);
            const float* Wb = Wres + (size_t)((l * 2 + blk) * 2 + 1) * 16384;
            const float* bb = bres + ((l * 2 + blk) * 2 + 1) * 128;
            #pragma unroll
            for (int jj = 0; jj < 4; jj++) a2[jj] = bb[jj * 32 + lane];
            for (int kk = 0; kk < 4; kk++) {
                float vv = a1[kk];
                for (int k2 = 0; k2 < 32; k2++) {
                    float vk = __shfl_sync(0xffffffffu, vv, k2);
                    int k = kk * 32 + k2;
                    #pragma unroll
                    for (int jj = 0; jj < 4; jj++)
                        a2[jj] = fmaf(Wb[(jj * 32 + lane) * 128 + k], vk, a2[jj]);
                }
            }
            #pragma unroll
            for (int jj = 0; jj < 4; jj++) h[jj] += a2[jj];
        }
        float accp = (lane < PMVAL) ? bf[l * (2 * PMVAL) + PMVAL + lane] : 0.f;
        for (int kk = 0; kk < 4; kk++) {
            float hv = h[kk];
            for (int k2 = 0; k2 < 32; k2++) {
                float vk = __shfl_sync(0xffffffffu, hv, k2);
                int k = kk * 32 + k2;
                if (lane < PMVAL)
                    accp = fmaf(Wf[((size_t)l * (2 * PMVAL) + PMVAL + lane) * 128 + k],
                                vk, accp);
            }
        }
        #pragma unroll
        for (int m = 0; m < PMVAL; m++) {
            float pm = __shfl_sync(0xffffffffu, accp, m);
            if (lane == src) p1out[m] = pm;
        }
    }
}

// ------------------------------ fused flow kernel ---------------------------
__global__ void __launch_bounds__(256)
flow_kernel(const float* __restrict__ z0in, const float* __restrict__ xin,
            const float* __restrict__ sigma,
            const float* __restrict__ n1w1, const float* __restrict__ n1b1,
            const float* __restrict__ n1w2, const float* __restrict__ n1b2,
            const float* __restrict__ n2w1, const float* __restrict__ n2b1,
            const float* __restrict__ n2w2, const float* __restrict__ n2b2,
            const float* __restrict__ made_W0, const float* __restrict__ made_b0,
            const float* __restrict__ made_Wres, const float* __restrict__ made_bres,
            const float* __restrict__ made_Wf, const float* __restrict__ made_bf,
            const float* __restrict__ lu_bias, const int* __restrict__ perms,
            float* __restrict__ out) {
    __shared__ float s1w[32], s1b[32], s1o[64], s1ob[2];
    __shared__ float s2w[128], s2b[32], s2o[64], s2ob[2];
    __shared__ float sld;
    __shared__ float sc_cw[NLAYER][9], sc_w[NLAYER][8], sc_ch[NLAYER][9];
    __shared__ float sc_h[NLAYER][8], sc_d[NLAYER][9];
    __shared__ float sc_invW[NLAYER][4], sc_b2[NLAYER][2];
    __shared__ int   sc_perm[NLAYER][2];

    const int tid  = threadIdx.x;
    const int lane = tid & 31;

    if (tid < 32) { s1w[tid] = n1w1[tid]; s1b[tid] = n1b1[tid]; s2b[tid] = n2b1[tid]; }
    if (tid < 64) { s1o[tid] = n1w2[tid]; s2o[tid] = n2w2[tid]; }
    if (tid < 128) s2w[tid] = n2w1[tid];
    if (tid < 2)  { s1ob[tid] = n1b2[tid]; s2ob[tid] = n2b2[tid]; }
    if (tid == 0) sld = g_ldinit;
    for (int i = tid; i < NLAYER * 9; i += 256) {
        sc_cw[i / 9][i % 9] = g_cw0[i];
        sc_ch[i / 9][i % 9] = g_ch0[i];
        sc_d [i / 9][i % 9] = g_d0[i];
    }
    for (int i = tid; i < NLAYER * 8; i += 256) {
        sc_w[i / 8][i % 8] = g_w0[i];
        sc_h[i / 8][i % 8] = g_h0[i];
    }
    for (int i = tid; i < NLAYER * 4; i += 256) sc_invW[i / 4][i % 4] = g_invW[i];
    for (int i = tid; i < NLAYER * 2; i += 256) {
        sc_b2[i / 2][i % 2]   = lu_bias[i];
        sc_perm[i / 2][i % 2] = perms[i];
    }
    __syncthreads();

    const int row = blockIdx.x * 256 + tid;

    // ---- prelude (fused) ----
    float sg = sigma[row];
    float2 zv = ((const float2*)z0in)[row];
    float2 xv = ((const float2*)xin)[row];
    float t0 = s1ob[0], t1 = s1ob[1];
    #pragma unroll
    for (int j = 0; j < 32; j++) {
        float hv = s1w[j] * sg + s1b[j];
        hv = hv * __frcp_rn(1.f + __expf(-hv));
        t0 += s1o[j] * hv;
        t1 += s1o[32 + j] * hv;
    }
    float zc0 = s2ob[0], zc1 = s2ob[1];
    #pragma unroll
    for (int j = 0; j < 32; j++) {
        float hv = s2w[4 * j] * zv.x + s2w[4 * j + 1] * zv.y
                 + s2w[4 * j + 2] * xv.x + s2w[4 * j + 3] * xv.y + s2b[j];
        hv = hv * __frcp_rn(1.f + __expf(-hv));
        zc0 += s2o[j] * hv;
        zc1 += s2o[32 + j] * hv;
    }
    float z0 = zc0 + t0;
    float z1 = zc1 + t1;
    float ld = sld;

    // ---- 16 layers ----
    #pragma unroll 1
    for (int l = 0; l < NLAYER; l++) {
        float out0, ldp0;
        rqs_reg(z0, sc_cw[l], sc_w[l], sc_ch[l], sc_h[l], sc_d[l], out0, ldp0);

        float uf = (out0 - TLO_F)  * TINVD_F;
        float uc = (out0 + 16.f) * TINVD_C;
        bool useF = (uf >= 0.f) && (uf < (float)(NODES_F - 1));
        bool useC = !useF && (uc >= 0.f) && (uc < (float)(NODES_C - 1));
        bool inr  = useF || useC;

        float out1 = z1, ldp1 = 0.f;
        if (inr) {
            float u = useF ? uf : uc;
            int i = (int)u;
            float f = u - (float)i;
            size_t nidx = useF ? ((size_t)l * NODES_F + i) : ((size_t)l * NODES_C + i);
            const float* s1p = (useF ? g_s1F : g_s1C) + nidx * 12;
            const float* kdp = (useF ? g_kdF : g_kdC) + nidx * 64;

            // stage 1: lerped ch -> bin k, yk, yk1
            float4 q0 = ((const float4*)s1p)[0];
            float4 q1 = ((const float4*)s1p)[1];
            float4 q2 = ((const float4*)s1p)[2];
            float d01, d23, d45, d6x, dlo, dhi;
            float chL[9];
            chL[0] = -TBV; chL[8] = TBV;
            unpack_h2(q1.w, d01, d23);
            chL[1] = fmaf(f, d01, q0.x);
            chL[2] = fmaf(f, d23, q0.y);
            unpack_h2(q2.x, d45, d6x);
            chL[3] = fmaf(f, d45, q0.z);
            chL[4] = fmaf(f, d6x, q0.w);
            unpack_h2(q2.y, dlo, dhi);
            chL[5] = fmaf(f, dlo, q1.x);
            chL[6] = fmaf(f, dhi, q1.y);
            unpack_h2(q2.z, dlo, dhi);
            chL[7] = fmaf(f, dlo, q1.z);

            bool inside = (z1 >= -TBV) && (z1 <= TBV);
            float yc = fminf(fmaxf(z1, -TBV), TBV);
            int k = 0;
            float yk = chL[0], yk1 = chL[1];
            #pragma unroll
            for (int j = 1; j < NBINS; j++) {
                bool c = yc >= chL[j];
                k   = c ? j : k;
                yk  = c ? chL[j] : yk;
                yk1 = c ? chL[j + 1] : yk1;
            }

            // stage 2: k-indexed cw/d pair with fp16 deltas
            const float4* e = (const float4*)(kdp + k * 8);
            float4 a = e[0];
            float4 b = e[1];
            float dcl, dch_, ddl, ddh;
            unpack_h2(a.z, dcl, dch_);
            unpack_h2(b.z, ddl, ddh);
            float xk  = fmaf(f, dcl,  a.x);
            float xk1 = fmaf(f, dch_, a.y);
            float dk  = fmaf(f, ddl,  b.x);
            float dk1 = fmaf(f, ddh,  b.y);

            float hk = yk1 - yk, wk = xk1 - xk;
            float sk = __fdividef(hk, wk);
            float dy = yc - yk;
            float t2 = dk + dk1 - 2.f * sk;
            float qa = dy * t2 + hk * (sk - dk);
            float qb = hk * dk - dy * t2;
            float qc = -sk * dy;
            float disc = fmaxf(qb * qb - 4.f * qa * qc, 0.f);
            float theta = __fdividef(2.f * qc, -qb - sqrtf(disc));
            float xo = theta * wk + xk;
            float om = 1.f - theta;
            float denom = sk + t2 * theta * om;
            float dnum = sk * sk * (dk1 * theta * theta + 2.f * sk * theta * om + dk * om * om);
            float ldf = __logf(__fdividef(dnum, denom * denom));
            out1 = inside ? xo : z1;
            ldp1 = inside ? -ldf : 0.f;
        }
        unsigned need = __ballot_sync(0xffffffffu, !inr);
        if (need) {
            float p1[PMVAL];
            made_fallback(need, out0, l, made_W0, made_b0, made_Wres, made_bres,
                          made_Wf, made_bf, p1, lane);
            if (!inr) {
                float cw9[9], ch9[9], dd9[9];
                knots_from_p1(p1, cw9, ch9, dd9);
                rqs_knots(z1, cw9, ch9, dd9, out1, ldp1);
            }
        }

        ld += ldp0 + ldp1;
        float v0 = out0 - sc_b2[l][0];
        float v1 = out1 - sc_b2[l][1];
        float zz0 = sc_invW[l][0] * v0 + sc_invW[l][1] * v1;
        float zz1 = sc_invW[l][2] * v0 + sc_invW[l][3] * v1;
        z0 = sc_perm[l][0] ? zz1 : zz0;
        z1 = sc_perm[l][1] ? zz1 : zz0;
    }

    ((float2*)out)[row] = make_float2(z0, z1);
    out[2 * BATCH + row] = ld;
}

// ------------------------------ launcher -----------------------------------
extern "C" void kernel_launch(void* const* d_in, const int* in_sizes, int n_in,
                              void* d_out, int out_size) {
    const float* z0      = (const float*)d_in[0];
    const float* x       = (const float*)d_in[1];
    const float* sigma   = (const float*)d_in[2];
    const float* n1_w1   = (const float*)d_in[3];
    const float* n1_b1   = (const float*)d_in[4];
    const float* n1_w2   = (const float*)d_in[5];
    const float* n1_b2   = (const float*)d_in[6];
    const float* n2_w1   = (const float*)d_in[7];
    const float* n2_b1   = (const float*)d_in[8];
    const float* n2_w2   = (const float*)d_in[9];
    const float* n2_b2   = (const float*)d_in[10];
    const float* made_W0 = (const float*)d_in[11];
    const float* made_b0 = (const float*)d_in[12];
    const float* made_Wres = (const float*)d_in[13];
    const float* made_bres = (const float*)d_in[14];
    const float* made_Wf   = (const float*)d_in[15];
    const float* made_bf   = (const float*)d_in[16];
    const float* lu_lower  = (const float*)d_in[17];
    const float* lu_upper  = (const float*)d_in[18];
    const float* lu_diag   = (const float*)d_in[19];
    const float* lu_bias   = (const float*)d_in[20];
    const int*   perms     = (const int*)d_in[21];
    float* out = (float*)d_out;

    cudaFuncSetAttribute(table_build_kernel,
                         cudaFuncAttributeMaxDynamicSharedMemorySize, DYN_SMEM);

    build_wimg_kernel<<<2048, 256>>>(made_Wres, made_Wf);
    setup_kernel<<<1, 32>>>(made_bf, lu_lower, lu_upper, lu_diag);
    table_build_kernel<<<NLAYER * BLKS_PER_LAYER, 256, DYN_SMEM>>>(
        made_W0, made_b0, made_bres, made_bf);
    pack_kernel<<<(NLAYER * NODES_T * 8 + 255) / 256, 256>>>();
    flow_kernel<<<BATCH / 256, 256>>>(
        z0, x, sigma, n1_w1, n1_b1, n1_w2, n1_b2,
        n2_w1, n2_b1, n2_w2, n2_b2,
        made_W0, made_b0, made_Wres, made_bres, made_Wf, made_bf,
        lu_bias, perms, out);
    (void)in_sizes; (void)n_in; (void)out_size;
}

// round 16
// speedup vs baseline: 1.5799x; 1.0444x over previous
#include <cuda_runtime.h>
#include <cuda_bf16.h>
#include <cuda_fp16.h>
#include <math.h>
#include <stdint.h>
#include <string.h>

// ---------------------------------------------------------------------------
// NeuralSplineFlow forward — bin-directed derived-knot table (R15) + R16:
//  * pack fused into table_build (blocks overlap by 1 node; knots staged in
//    smem; S1/KD written directly — pack kernel and g_kt round-trip deleted),
//  * build_wimg uses an smem-tiled transpose (coalesced reads AND stores).
// Flow kernel and table numerics identical to R15.
// ---------------------------------------------------------------------------

#define BATCH   262144
#define NLAYER  16
#define HDIM    128
#define NBINS   8
#define PMVAL   23
#define TBV     3.0f
#define MINWV   0.001f
#define MINDV   0.001f
#define LUEPS   0.001f
#define INV_SQH 0.08838834764831843f   // 1/sqrt(128)

// dual-resolution table
#define NODES_F 833                    // [-3.25, 3.25], delta 1/128
#define NODES_C 129                    // [-16,16], delta 1/4
#define FINE_BLKS 7                    // ceil(832/127)
#define COARSE_BLKS 2                  // ceil(128/127)
#define BLKS_PER_LAYER (FINE_BLKS + COARSE_BLKS)   // 9 -> 144 blocks = 1 wave
#define TLO_F    (-3.25f)
#define TINVD_F  128.0f
#define TDELTA_F 0.0078125f
#define TINVD_C  4.0f
#define TDELTA_C 0.25f

// SMEM geometry for the table-build (mma) kernel
#define KSTRIDE   136
#define ROWB      (KSTRIDE * 2)
#define ACT_BYTES (HDIM * ROWB)          // 34816
#define WMAT_ELEMS (HDIM * KSTRIDE)
#define WSLOT_BYTES (2 * ACT_BYTES)      // 69632
#define WF_STRIDE 40
#define WF_HALF   (HDIM * WF_STRIDE)
#define WF_BYTES  (2 * WF_HALF * 2)

#define OFF_ACTHI 0
#define OFF_ACTLO 34816
#define OFF_SLOT0 69632
#define OFF_SLOT1 139264
#define OFF_P1    139264
#define DYN_SMEM  208896

// ----------------------------- device scratch ------------------------------
__device__ __align__(16) uint16_t g_Wimg[NLAYER * 4 * 2 * WMAT_ELEMS];
__device__ __align__(16) uint16_t g_Wfimg[NLAYER * 2 * WF_HALF];
__device__ __align__(16) float g_s1F[NLAYER * NODES_F * 12];
__device__ __align__(16) float g_s1C[NLAYER * NODES_C * 12];
__device__ __align__(16) float g_kdF[NLAYER * NODES_F * 64];
__device__ __align__(16) float g_kdC[NLAYER * NODES_C * 64];
__device__ float g_cw0[NLAYER * 9];
__device__ float g_w0[NLAYER * 8];
__device__ float g_ch0[NLAYER * 9];
__device__ float g_h0[NLAYER * 8];
__device__ float g_d0[NLAYER * 9];
__device__ float g_invW[NLAYER * 4];
__device__ float g_ldinit;

// ----------------------------- PTX helpers ---------------------------------
__device__ __forceinline__ uint32_t smem_u32(const void* p) {
    uint32_t a;
    asm("{ .reg .u64 t; cvta.to.shared.u64 t, %1; cvt.u32.u64 %0, t; }"
        : "=r"(a) : "l"(p));
    return a;
}
__device__ __forceinline__ void ldmA4(uint32_t a[4], uint32_t addr) {
    asm volatile("ldmatrix.sync.aligned.m8n8.x4.shared.b16 {%0,%1,%2,%3}, [%4];"
        : "=r"(a[0]), "=r"(a[1]), "=r"(a[2]), "=r"(a[3]) : "r"(addr));
}
__device__ __forceinline__ void ldmB4t(uint32_t b[4], uint32_t addr) {
    asm volatile("ldmatrix.sync.aligned.m8n8.x4.trans.shared.b16 {%0,%1,%2,%3}, [%4];"
        : "=r"(b[0]), "=r"(b[1]), "=r"(b[2]), "=r"(b[3]) : "r"(addr));
}
__device__ __forceinline__ void mmabf(float d[4], const uint32_t a[4],
                                      uint32_t b0, uint32_t b1) {
    asm volatile("mma.sync.aligned.m16n8k16.row.col.f32.bf16.bf16.f32 "
        "{%0,%1,%2,%3}, {%4,%5,%6,%7}, {%8,%9}, {%0,%1,%2,%3};"
        : "+f"(d[0]), "+f"(d[1]), "+f"(d[2]), "+f"(d[3])
        : "r"(a[0]), "r"(a[1]), "r"(a[2]), "r"(a[3]), "r"(b0), "r"(b1));
}
__device__ __forceinline__ void cpasync16(uint32_t dst, const void* src) {
    asm volatile("cp.async.cg.shared.global [%0], [%1], 16;"
                 :: "r"(dst), "l"(src));
}
#define CP_COMMIT() asm volatile("cp.async.commit_group;" ::: "memory")
#define CP_WAIT0()  asm volatile("cp.async.wait_group 0;" ::: "memory")

__device__ __forceinline__ float pack_h2(float a, float b) {
    __half2 h = __floats2half2_rn(a, b);
    uint32_t u;
    memcpy(&u, &h, 4);
    return __uint_as_float(u);
}
__device__ __forceinline__ void unpack_h2(float p, float& lo, float& hi) {
    uint32_t u = __float_as_uint(p);
    __half2 h;
    memcpy(&h, &u, 4);
    lo = __low2float(h);
    hi = __high2float(h);
}

// ----------------------------- math helpers --------------------------------
__device__ __forceinline__ float softplusf(float x) {
    return fmaxf(x, 0.f) + log1pf(expf(-fabsf(x)));
}
__device__ __forceinline__ float softplus_fast(float x) {
    return fmaxf(x, 0.f) + __logf(1.f + __expf(-fabsf(x)));
}

__device__ void build_params(const float* uw, const float* uh, const float* ud,
                             float* cw, float* w, float* ch, float* hh, float* dd) {
    {
        float mx = uw[0];
        #pragma unroll
        for (int k = 1; k < NBINS; k++) mx = fmaxf(mx, uw[k]);
        float e[NBINS]; float s = 0.f;
        #pragma unroll
        for (int k = 0; k < NBINS; k++) { e[k] = expf(uw[k] - mx); s += e[k]; }
        float inv = 1.f / s;
        cw[0] = -TBV; float cum = 0.f;
        #pragma unroll
        for (int k = 0; k < NBINS; k++) {
            float wk = MINWV + (1.f - MINWV * NBINS) * e[k] * inv;
            cum += wk;
            cw[k + 1] = 2.f * TBV * cum - TBV;
        }
        cw[NBINS] = TBV;
        #pragma unroll
        for (int k = 0; k < NBINS; k++) w[k] = cw[k + 1] - cw[k];
    }
    {
        float mx = uh[0];
        #pragma unroll
        for (int k = 1; k < NBINS; k++) mx = fmaxf(mx, uh[k]);
        float e[NBINS]; float s = 0.f;
        #pragma unroll
        for (int k = 0; k < NBINS; k++) { e[k] = expf(uh[k] - mx); s += e[k]; }
        float inv = 1.f / s;
        ch[0] = -TBV; float cum = 0.f;
        #pragma unroll
        for (int k = 0; k < NBINS; k++) {
            float hk = MINWV + (1.f - MINWV * NBINS) * e[k] * inv;
            cum += hk;
            ch[k + 1] = 2.f * TBV * cum - TBV;
        }
        ch[NBINS] = TBV;
        #pragma unroll
        for (int k = 0; k < NBINS; k++) hh[k] = ch[k + 1] - ch[k];
    }
    dd[0] = 1.0f;
    #pragma unroll
    for (int k = 0; k < 7; k++) dd[k + 1] = MINDV + softplusf(ud[k]);
    dd[NBINS] = 1.0f;
}

__device__ __forceinline__ void rqs_reg(float y, const float cw[9], const float w[8],
                                        const float ch[9], const float hh[8],
                                        const float dd[9], float& xout, float& ldout) {
    bool inside = (y >= -TBV) && (y <= TBV);
    float yc = fminf(fmaxf(y, -TBV), TBV);
    float yk = ch[0], hk = hh[0], xk = cw[0], wk = w[0], dk = dd[0], dk1 = dd[1];
    #pragma unroll
    for (int k = 1; k < NBINS; k++) {
        bool c = yc >= ch[k];
        yk  = c ? ch[k]     : yk;
        hk  = c ? hh[k]     : hk;
        xk  = c ? cw[k]     : xk;
        wk  = c ? w[k]      : wk;
        dk  = c ? dd[k]     : dk;
        dk1 = c ? dd[k + 1] : dk1;
    }
    float sk = __fdividef(hk, wk);
    float dy = yc - yk;
    float t2 = dk + dk1 - 2.f * sk;
    float qa = dy * t2 + hk * (sk - dk);
    float qb = hk * dk - dy * t2;
    float qc = -sk * dy;
    float disc = fmaxf(qb * qb - 4.f * qa * qc, 0.f);
    float theta = __fdividef(2.f * qc, -qb - sqrtf(disc));
    float xo = theta * wk + xk;
    float om = 1.f - theta;
    float denom = sk + t2 * theta * om;
    float dnum = sk * sk * (dk1 * theta * theta + 2.f * sk * theta * om + dk * om * om);
    float ldf = __logf(__fdividef(dnum, denom * denom));
    xout  = inside ? xo : y;
    ldout = inside ? -ldf : 0.f;
}

__device__ __forceinline__ void rqs_knots(float y, const float cw[9], const float ch[9],
                                          const float dd[9], float& xout, float& ldout) {
    bool inside = (y >= -TBV) && (y <= TBV);
    float yc = fminf(fmaxf(y, -TBV), TBV);
    float yk = ch[0], yk1 = ch[1], xk = cw[0], xk1 = cw[1], dk = dd[0], dk1 = dd[1];
    #pragma unroll
    for (int k = 1; k < NBINS; k++) {
        bool c = yc >= ch[k];
        yk  = c ? ch[k]     : yk;
        yk1 = c ? ch[k + 1] : yk1;
        xk  = c ? cw[k]     : xk;
        xk1 = c ? cw[k + 1] : xk1;
        dk  = c ? dd[k]     : dk;
        dk1 = c ? dd[k + 1] : dk1;
    }
    float hk = yk1 - yk, wk = xk1 - xk;
    float sk = __fdividef(hk, wk);
    float dy = yc - yk;
    float t2 = dk + dk1 - 2.f * sk;
    float qa = dy * t2 + hk * (sk - dk);
    float qb = hk * dk - dy * t2;
    float qc = -sk * dy;
    float disc = fmaxf(qb * qb - 4.f * qa * qc, 0.f);
    float theta = __fdividef(2.f * qc, -qb - sqrtf(disc));
    float xo = theta * wk + xk;
    float om = 1.f - theta;
    float denom = sk + t2 * theta * om;
    float dnum = sk * sk * (dk1 * theta * theta + 2.f * sk * theta * om + dk * om * om);
    float ldf = __logf(__fdividef(dnum, denom * denom));
    xout  = inside ? xo : y;
    ldout = inside ? -ldf : 0.f;
}

__device__ __forceinline__ void knots_from_p1(const float* p1, float cw[9],
                                              float ch[9], float dd[9]) {
    float uw[8], uh[8];
    #pragma unroll
    for (int k = 0; k < 8; k++) { uw[k] = p1[k] * INV_SQH; uh[k] = p1[8 + k] * INV_SQH; }
    float mw = uw[0], mh = uh[0];
    #pragma unroll
    for (int k = 1; k < 8; k++) { mw = fmaxf(mw, uw[k]); mh = fmaxf(mh, uh[k]); }
    float ew[8], eh[8], sw = 0.f, sh = 0.f;
    #pragma unroll
    for (int k = 0; k < 8; k++) {
        ew[k] = __expf(uw[k] - mw); sw += ew[k];
        eh[k] = __expf(uh[k] - mh); sh += eh[k];
    }
    float iw = __fdividef(1.f - MINWV * NBINS, sw);
    float ih = __fdividef(1.f - MINWV * NBINS, sh);
    cw[0] = -TBV; ch[0] = -TBV;
    float cumw = 0.f, cumh = 0.f;
    #pragma unroll
    for (int k = 0; k < 7; k++) {
        cumw += MINWV + iw * ew[k];
        cumh += MINWV + ih * eh[k];
        cw[k + 1] = fmaf(2.f * TBV, cumw, -TBV);
        ch[k + 1] = fmaf(2.f * TBV, cumh, -TBV);
    }
    cw[8] = TBV; ch[8] = TBV;
    dd[0] = 1.f; dd[8] = 1.f;
    #pragma unroll
    for (int k = 0; k < 7; k++) dd[k + 1] = MINDV + softplus_fast(p1[16 + k]);
}

__device__ __forceinline__ void split2(float a, float b, uint32_t& hi, uint32_t& lo) {
    __nv_bfloat16 ah = __float2bfloat16(a), bh = __float2bfloat16(b);
    __nv_bfloat16 al = __float2bfloat16(a - __bfloat162float(ah));
    __nv_bfloat16 bl = __float2bfloat16(b - __bfloat162float(bh));
    hi = (uint32_t)__bfloat16_as_ushort(ah) | ((uint32_t)__bfloat16_as_ushort(bh) << 16);
    lo = (uint32_t)__bfloat16_as_ushort(al) | ((uint32_t)__bfloat16_as_ushort(bl) << 16);
}

// ------------------------------ setup kernels ------------------------------
// smem-tiled transpose: coalesced reads AND coalesced 2-byte stores.
// grid part 1: Wres, 64 matrices x (4 k-tiles x 5 n-tiles) = 1280 blocks
// grid part 2: Wf,   16 layers  x (4 k-tiles x 2 n-tiles) = 128 blocks
__global__ void build_wimg_kernel(const float* __restrict__ Wres,
                                  const float* __restrict__ Wf) {
    __shared__ float tileS[32][33];
    const int tx = threadIdx.x;        // 0..31
    const int ty = threadIdx.y;        // 0..7
    int tIdx = blockIdx.x;
    if (tIdx < 64 * 20) {
        int mg = tIdx / 20;
        int t  = tIdx % 20;
        int kt = t / 5, nt = t % 5;
        int k0 = kt * 32, n0 = nt * 32;
        #pragma unroll
        for (int j = 0; j < 4; j++) {
            int n = n0 + ty + j * 8;
            float v = (n < HDIM) ? Wres[mg * 16384 + n * HDIM + k0 + tx] : 0.f;
            tileS[ty + j * 8][tx] = v;
        }
        __syncthreads();
        #pragma unroll
        for (int j = 0; j < 4; j++) {
            int k = k0 + ty + j * 8;
            int n = n0 + tx;
            if (n < KSTRIDE) {
                float v = tileS[tx][ty + j * 8];
                __nv_bfloat16 h = __float2bfloat16(v);
                __nv_bfloat16 l = __float2bfloat16(v - __bfloat162float(h));
                int base = (mg * 2) * WMAT_ELEMS + k * KSTRIDE + n;
                g_Wimg[base]              = __bfloat16_as_ushort(h);
                g_Wimg[base + WMAT_ELEMS] = __bfloat16_as_ushort(l);
            }
        }
    } else {
        int t2 = tIdx - 64 * 20;
        int ly = t2 / 8;
        int tt = t2 % 8;
        int kt = tt / 2, nt = tt % 2;
        int k0 = kt * 32, n0 = nt * 32;
        #pragma unroll
        for (int j = 0; j < 4; j++) {
            int n = n0 + ty + j * 8;
            float v = (n < PMVAL)
                    ? Wf[(ly * (2 * PMVAL) + PMVAL + n) * HDIM + k0 + tx] : 0.f;
            tileS[ty + j * 8][tx] = v;
        }
        __syncthreads();
        #pragma unroll
        for (int j = 0; j < 4; j++) {
            int k = k0 + ty + j * 8;
            int n = n0 + tx;
            if (n < WF_STRIDE) {
                float v = tileS[tx][ty + j * 8];
                __nv_bfloat16 h = __float2bfloat16(v);
                __nv_bfloat16 l = __float2bfloat16(v - __bfloat162float(h));
                int base = (ly * 2) * WF_HALF + k * WF_STRIDE + n;
                g_Wfimg[base]           = __bfloat16_as_ushort(h);
                g_Wfimg[base + WF_HALF] = __bfloat16_as_ushort(l);
            }
        }
    }
}

__global__ void setup_kernel(const float* __restrict__ made_bf,
                             const float* __restrict__ lu_lower,
                             const float* __restrict__ lu_upper,
                             const float* __restrict__ lu_diag) {
    __shared__ float sldl[NLAYER];
    int i = threadIdx.x;
    if (i < NLAYER) {
        const float* bfL = made_bf + i * (2 * PMVAL);
        float uw[8], uh[8], ud[7];
        #pragma unroll
        for (int k = 0; k < 8; k++) { uw[k] = bfL[k] * INV_SQH; uh[k] = bfL[8 + k] * INV_SQH; }
        #pragma unroll
        for (int k = 0; k < 7; k++) ud[k] = bfL[16 + k];
        build_params(uw, uh, ud, g_cw0 + 9 * i, g_w0 + 8 * i,
                     g_ch0 + 9 * i, g_h0 + 8 * i, g_d0 + 9 * i);
        float l = lu_lower[i], u = lu_upper[i];
        float d0 = softplusf(lu_diag[2 * i]) + LUEPS;
        float d1 = softplusf(lu_diag[2 * i + 1]) + LUEPS;
        float invdet = 1.f / (d0 * d1);
        g_invW[4 * i + 0] = (l * u + d1) * invdet;
        g_invW[4 * i + 1] = -u * invdet;
        g_invW[4 * i + 2] = -l * d0 * invdet;
        g_invW[4 * i + 3] = d0 * invdet;
        sldl[i] = logf(d0) + logf(d1);
    }
    __syncthreads();
    if (i == 0) {
        float s = 0.f;
        for (int j = 0; j < NLAYER; j++) s += sldl[j];
        g_ldinit = -s;
    }
}

// ------------------------- table-build (mma) kernel -------------------------
__device__ __forceinline__ void prefetch_w(uint32_t dst_u, const uint16_t* gsrc,
                                           int chunks, int tid) {
    const char* s = (const char*)gsrc;
    for (int i = tid; i < chunks; i += 256)
        cpasync16(dst_u + i * 16, s + i * 16);
    CP_COMMIT();
}

__global__ void __launch_bounds__(256, 1)
table_build_kernel(const float* __restrict__ made_W0,
                   const float* __restrict__ made_b0,
                   const float* __restrict__ made_bres,
                   const float* __restrict__ made_bf) {
    extern __shared__ char dynsm[];
    __shared__ float s_bias[4][HDIM];
    __shared__ float s_out0[HDIM];
    __shared__ float s_w0col[HDIM], s_b0[HDIM];

    const int layer = blockIdx.x / BLKS_PER_LAYER;
    const int tile  = blockIdx.x % BLKS_PER_LAYER;
    const bool fineB = (tile < FINE_BLKS);
    const int tid   = threadIdx.x;
    const int lane  = tid & 31;
    const int w     = tid >> 5;

    const uint32_t base_u  = smem_u32(dynsm);
    const uint32_t actHi_u = base_u + OFF_ACTHI;
    const uint32_t slot_u[2] = { base_u + OFF_SLOT0, base_u + OFF_SLOT1 };

    prefetch_w(slot_u[0], g_Wimg + (size_t)(layer * 4) * (2 * WMAT_ELEMS),
               WSLOT_BYTES / 16, tid);

    if (tid < HDIM) {
        s_w0col[tid] = made_W0[(layer * HDIM + tid) * 2];
        s_b0[tid]    = made_b0[layer * HDIM + tid];
        // blocks overlap by 1 node: 127 packed entries per block
        int node;
        float x;
        if (fineB) {
            node = min(tile * 127 + tid, NODES_F - 1);
            x = TLO_F + (float)node * TDELTA_F;
        } else {
            node = min((tile - FINE_BLKS) * 127 + tid, NODES_C - 1);
            x = -16.f + (float)node * TDELTA_C;
        }
        s_out0[tid] = x;
    }
    for (int i = tid; i < 4 * HDIM; i += 256)
        s_bias[i >> 7][i & 127] = made_bres[layer * 4 * HDIM + i];
    __syncthreads();

    const int r0 = w * 16 + (lane >> 2);
    const int r1 = r0 + 8;
    const int cB = (lane & 3) * 2;
    const uint32_t o0 = (uint32_t)r0 * ROWB + cB * 2;
    const uint32_t o1 = (uint32_t)r1 * ROWB + cB * 2;

    float H[64];
    {
        float oa = s_out0[r0], ob = s_out0[r1];
        #pragma unroll
        for (int t = 0; t < 16; t++) {
            int c = t * 8 + cB;
            float2 wc = *(const float2*)&s_w0col[c];
            float2 bc = *(const float2*)&s_b0[c];
            float h0 = fmaf(oa, wc.x, bc.x), h1 = fmaf(oa, wc.y, bc.y);
            float h2 = fmaf(ob, wc.x, bc.x), h3 = fmaf(ob, wc.y, bc.y);
            H[t * 4] = h0; H[t * 4 + 1] = h1; H[t * 4 + 2] = h2; H[t * 4 + 3] = h3;
            uint32_t hi0, lo0, hi1, lo1;
            split2(fmaxf(h0, 0.f), fmaxf(h1, 0.f), hi0, lo0);
            split2(fmaxf(h2, 0.f), fmaxf(h3, 0.f), hi1, lo1);
            *(uint32_t*)(dynsm + OFF_ACTHI + o0 + t * 16) = hi0;
            *(uint32_t*)(dynsm + OFF_ACTHI + o1 + t * 16) = hi1;
            *(uint32_t*)(dynsm + OFF_ACTLO + o0 + t * 16) = lo0;
            *(uint32_t*)(dynsm + OFF_ACTLO + o1 + t * 16) = lo1;
        }
    }
    CP_WAIT0();
    __syncthreads();

    const uint32_t aHiBase = actHi_u + (uint32_t)(w * 16 + (lane & 15)) * ROWB
                             + ((lane >> 4) * 16);
    const uint32_t aLoBase = aHiBase + ACT_BYTES;
    const uint32_t bOff    = (uint32_t)(lane & 15) * ROWB + ((lane >> 4) * 16);
    const uint32_t wfOff   = (uint32_t)(lane & 15) * (WF_STRIDE * 2) + ((lane >> 4) * 16);

    #pragma unroll 1
    for (int g = 0; g < 4; g++) {
        if (g < 3)
            prefetch_w(slot_u[(g + 1) & 1],
                       g_Wimg + (size_t)(layer * 4 + g + 1) * (2 * WMAT_ELEMS),
                       WSLOT_BYTES / 16, tid);
        else
            prefetch_w(slot_u[0], g_Wfimg + (size_t)layer * (2 * WF_HALF),
                       WF_BYTES / 16, tid);

        __syncwarp();
        uint32_t Ah[8][4], Al[8][4];
        #pragma unroll
        for (int kc = 0; kc < 8; kc++) {
            ldmA4(Ah[kc], aHiBase + kc * 32);
            ldmA4(Al[kc], aLoBase + kc * 32);
        }
        const uint32_t wbase = slot_u[g & 1] + bOff;

        #pragma unroll
        for (int tp = 0; tp < 8; tp++) {
            float D0[4] = {0.f, 0.f, 0.f, 0.f};
            float D1[4] = {0.f, 0.f, 0.f, 0.f};
            #pragma unroll
            for (int kc = 0; kc < 8; kc++) {
                uint32_t bh[4], bl[4];
                ldmB4t(bh, wbase + kc * (16 * ROWB) + tp * 32);
                ldmB4t(bl, wbase + ACT_BYTES + kc * (16 * ROWB) + tp * 32);
                mmabf(D0, Ah[kc], bh[0], bh[1]);
                mmabf(D0, Al[kc], bh[0], bh[1]);
                mmabf(D0, Ah[kc], bl[0], bl[1]);
                mmabf(D1, Ah[kc], bh[2], bh[3]);
                mmabf(D1, Al[kc], bh[2], bh[3]);
                mmabf(D1, Ah[kc], bl[2], bl[3]);
            }
            #pragma unroll
            for (int q = 0; q < 2; q++) {
                const int t = tp * 2 + q;
                float* D = q ? D1 : D0;
                float2 bb = *(const float2*)&s_bias[g][t * 8 + cB];
                float v0, v1, v2, v3;
                if ((g & 1) == 0) {
                    v0 = fmaxf(D[0] + bb.x, 0.f);
                    v1 = fmaxf(D[1] + bb.y, 0.f);
                    v2 = fmaxf(D[2] + bb.x, 0.f);
                    v3 = fmaxf(D[3] + bb.y, 0.f);
                } else {
                    float n0 = H[t * 4]     + D[0] + bb.x;
                    float n1 = H[t * 4 + 1] + D[1] + bb.y;
                    float n2 = H[t * 4 + 2] + D[2] + bb.x;
                    float n3 = H[t * 4 + 3] + D[3] + bb.y;
                    H[t * 4] = n0; H[t * 4 + 1] = n1;
                    H[t * 4 + 2] = n2; H[t * 4 + 3] = n3;
                    if (g == 3) { v0 = n0; v1 = n1; v2 = n2; v3 = n3; }
                    else { v0 = fmaxf(n0, 0.f); v1 = fmaxf(n1, 0.f);
                           v2 = fmaxf(n2, 0.f); v3 = fmaxf(n3, 0.f); }
                }
                uint32_t hi0, lo0, hi1, lo1;
                split2(v0, v1, hi0, lo0);
                split2(v2, v3, hi1, lo1);
                *(uint32_t*)(dynsm + OFF_ACTHI + o0 + t * 16) = hi0;
                *(uint32_t*)(dynsm + OFF_ACTHI + o1 + t * 16) = hi1;
                *(uint32_t*)(dynsm + OFF_ACTLO + o0 + t * 16) = lo0;
                *(uint32_t*)(dynsm + OFF_ACTLO + o1 + t * 16) = lo1;
            }
        }
        CP_WAIT0();
        __syncthreads();
    }

    // Wf GEMM
    {
        __syncwarp();
        uint32_t Ah[8][4], Al[8][4];
        #pragma unroll
        for (int kc = 0; kc < 8; kc++) {
            ldmA4(Ah[kc], aHiBase + kc * 32);
            ldmA4(Al[kc], aLoBase + kc * 32);
        }
        const uint32_t wfb = slot_u[0] + wfOff;
        float* p1 = (float*)(dynsm + OFF_P1);
        #pragma unroll
        for (int tp = 0; tp < 2; tp++) {
            float D0[4] = {0.f, 0.f, 0.f, 0.f};
            float D1[4] = {0.f, 0.f, 0.f, 0.f};
            #pragma unroll
            for (int kc = 0; kc < 8; kc++) {
                uint32_t bh[4], bl[4];
                ldmB4t(bh, wfb + kc * (16 * WF_STRIDE * 2) + tp * 32);
                ldmB4t(bl, wfb + 2 * WF_HALF + kc * (16 * WF_STRIDE * 2) + tp * 32);
                mmabf(D0, Ah[kc], bh[0], bh[1]);
                mmabf(D0, Al[kc], bh[0], bh[1]);
                mmabf(D0, Ah[kc], bl[0], bl[1]);
                mmabf(D1, Ah[kc], bh[2], bh[3]);
                mmabf(D1, Al[kc], bh[2], bh[3]);
                mmabf(D1, Ah[kc], bl[2], bl[3]);
            }
            int c0 = tp * 16 + cB;
            p1[r0 * 26 + c0] = D0[0]; p1[r0 * 26 + c0 + 1] = D0[1];
            p1[r1 * 26 + c0] = D0[2]; p1[r1 * 26 + c0 + 1] = D0[3];
            if (tp == 0) {
                p1[r0 * 26 + c0 + 8] = D1[0]; p1[r0 * 26 + c0 + 9] = D1[1];
                p1[r1 * 26 + c0 + 8] = D1[2]; p1[r1 * 26 + c0 + 9] = D1[3];
            }
        }
    }
    __syncthreads();

    // derive knots into smem (slot0 region is free after the Wf GEMM)
    float* ksm = (float*)(dynsm + OFF_SLOT0);   // [128][24]
    if (tid < HDIM) {
        const float* p1r = (const float*)(dynsm + OFF_P1) + tid * 26;
        const float* bf1 = made_bf + layer * (2 * PMVAL) + PMVAL;
        float uw[8], uh[8], ud[7];
        #pragma unroll
        for (int k = 0; k < 8; k++) {
            uw[k] = (p1r[k]     + bf1[k])     * INV_SQH;
            uh[k] = (p1r[8 + k] + bf1[8 + k]) * INV_SQH;
        }
        #pragma unroll
        for (int k = 0; k < 7; k++) ud[k] = p1r[16 + k] + bf1[16 + k];
        float cw[9], ww[8], chh[9], hh2[8], dd[9];
        build_params(uw, uh, ud, cw, ww, chh, hh2, dd);
        float* row = ksm + tid * 24;
        #pragma unroll
        for (int k = 0; k < 7; k++) {
            row[k]      = cw[k + 1];
            row[7 + k]  = chh[k + 1];
            row[14 + k] = dd[k + 1];
        }
    }
    __syncthreads();

    // fused pack: thread tid packs entry for node (block_start + tid) using
    // smem knots [tid] and [tid+1]. 127 entries per block.
    if (tid < 127) {
        int i;
        bool valid;
        if (fineB) { i = tile * 127 + tid;                valid = (i <= NODES_F - 2); }
        else       { i = (tile - FINE_BLKS) * 127 + tid;  valid = (i <= NODES_C - 2); }
        if (valid) {
            const float* cur = ksm + tid * 24;
            const float* nxt = ksm + (tid + 1) * 24;
            // S1
            float s1[12];
            #pragma unroll
            for (int k = 0; k < 7; k++) s1[k] = cur[7 + k];
            float dch[7];
            #pragma unroll
            for (int k = 0; k < 7; k++) dch[k] = nxt[7 + k] - cur[7 + k];
            s1[7]  = pack_h2(dch[0], dch[1]);
            s1[8]  = pack_h2(dch[2], dch[3]);
            s1[9]  = pack_h2(dch[4], dch[5]);
            s1[10] = pack_h2(dch[6], 0.f);
            s1[11] = 0.f;
            float* s1dst = fineB ? g_s1F + ((size_t)layer * NODES_F + i) * 12
                                 : g_s1C + ((size_t)layer * NODES_C + i) * 12;
            #pragma unroll
            for (int q = 0; q < 3; q++)
                ((float4*)s1dst)[q] = ((const float4*)s1)[q];
            // KD: 8 entries
            float cwc[9], cwn[9], dfc[9], dfn[9];
            cwc[0] = -TBV; cwc[8] = TBV; cwn[0] = -TBV; cwn[8] = TBV;
            dfc[0] = 1.f;  dfc[8] = 1.f;  dfn[0] = 1.f;  dfn[8] = 1.f;
            #pragma unroll
            for (int k = 0; k < 7; k++) {
                cwc[k + 1] = cur[k];       cwn[k + 1] = nxt[k];
                dfc[k + 1] = cur[14 + k];  dfn[k + 1] = nxt[14 + k];
            }
            float* kddst = fineB ? g_kdF + ((size_t)layer * NODES_F + i) * 64
                                 : g_kdC + ((size_t)layer * NODES_C + i) * 64;
            #pragma unroll
            for (int k = 0; k < 8; k++) {
                float e[8];
                e[0] = cwc[k]; e[1] = cwc[k + 1];
                e[2] = pack_h2(cwn[k] - cwc[k], cwn[k + 1] - cwc[k + 1]);
                e[3] = 0.f;
                e[4] = dfc[k]; e[5] = dfc[k + 1];
                e[6] = pack_h2(dfn[k] - dfc[k], dfn[k + 1] - dfc[k + 1]);
                e[7] = 0.f;
                ((float4*)(kddst + k * 8))[0] = ((const float4*)e)[0];
                ((float4*)(kddst + k * 8))[1] = ((const float4*)e)[1];
            }
        }
    }
}

// ------------------------- exact MLP fallback (rare) ------------------------
__device__ void made_fallback(unsigned need, float out0_self, int l,
                              const float* __restrict__ W0,
                              const float* __restrict__ b0,
                              const float* __restrict__ Wres,
                              const float* __restrict__ bres,
                              const float* __restrict__ Wf,
                              const float* __restrict__ bf,
                              float* p1out, int lane) {
    while (need) {
        int src = __ffs(need) - 1;
        need &= need - 1;
        float x0 = __shfl_sync(0xffffffffu, out0_self, src);
        float h[4];
        #pragma unroll
        for (int jj = 0; jj < 4; jj++) {
            int j = jj * 32 + lane;
            h[jj] = fmaf(x0, W0[(l * HDIM + j) * 2], b0[l * HDIM + j]);
        }
        #pragma unroll 1
        for (int blk = 0; blk < 2; blk++) {
            float v[4], a1[4], a2[4];
            #pragma unroll
            for (int jj = 0; jj < 4; jj++) v[jj] = fmaxf(h[jj], 0.f);
            const float* Wa = Wres + (size_t)((l * 2 + blk) * 2 + 0) * 16384;
            const float* ba = bres + ((l * 2 + blk) * 2 + 0) * 128;
            #pragma unroll
            for (int jj = 0; jj < 4; jj++) a1[jj] = ba[jj * 32 + lane];
            for (int kk = 0; kk < 4; kk++) {
                float vv = v[kk];
                for (int k2 = 0; k2 < 32; k2++) {
                    float vk = __shfl_sync(0xffffffffu, vv, k2);
                    int k = kk * 32 + k2;
                    #pragma unroll
                    for (int jj = 0; jj < 4; jj++)
                        a1[jj] = fmaf(Wa[(jj * 32 + lane) * 128 + k], vk, a1[jj]);
                }
            }
            #pragma unroll
            for (int jj = 0; jj < 4; jj++) a1[jj] = fmaxf(a1[jj], 0.f);
            const float* Wb = Wres + (size_t)((l * 2 + blk) * 2 + 1) * 16384;
            const float* bb = bres + ((l * 2 + blk) * 2 + 1) * 128;
            #pragma unroll
            for (int jj = 0; jj < 4; jj++) a2[jj] = bb[jj * 32 + lane];
            for (int kk = 0; kk < 4; kk++) {
                float vv = a1[kk];
                for (int k2 = 0; k2 < 32; k2++) {
                    float vk = __shfl_sync(0xffffffffu, vv, k2);
                    int k = kk * 32 + k2;
                    #pragma unroll
                    for (int jj = 0; jj < 4; jj++)
                        a2[jj] = fmaf(Wb[(jj * 32 + lane) * 128 + k], vk, a2[jj]);
                }
            }
            #pragma unroll
            for (int jj = 0; jj < 4; jj++) h[jj] += a2[jj];
        }
        float accp = (lane < PMVAL) ? bf[l * (2 * PMVAL) + PMVAL + lane] : 0.f;
        for (int kk = 0; kk < 4; kk++) {
            float hv = h[kk];
            for (int k2 = 0; k2 < 32; k2++) {
                float vk = __shfl_sync(0xffffffffu, hv, k2);
                int k = kk * 32 + k2;
                if (lane < PMVAL)
                    accp = fmaf(Wf[((size_t)l * (2 * PMVAL) + PMVAL + lane) * 128 + k],
                                vk, accp);
            }
        }
        #pragma unroll
        for (int m = 0; m < PMVAL; m++) {
            float pm = __shfl_sync(0xffffffffu, accp, m);
            if (lane == src) p1out[m] = pm;
        }
    }
}

// ------------------------------ fused flow kernel ---------------------------
__global__ void __launch_bounds__(256)
flow_kernel(const float* __restrict__ z0in, const float* __restrict__ xin,
            const float* __restrict__ sigma,
            const float* __restrict__ n1w1, const float* __restrict__ n1b1,
            const float* __restrict__ n1w2, const float* __restrict__ n1b2,
            const float* __restrict__ n2w1, const float* __restrict__ n2b1,
            const float* __restrict__ n2w2, const float* __restrict__ n2b2,
            const float* __restrict__ made_W0, const float* __restrict__ made_b0,
            const float* __restrict__ made_Wres, const float* __restrict__ made_bres,
            const float* __restrict__ made_Wf, const float* __restrict__ made_bf,
            const float* __restrict__ lu_bias, const int* __restrict__ perms,
            float* __restrict__ out) {
    __shared__ float s1w[32], s1b[32], s1o[64], s1ob[2];
    __shared__ float s2w[128], s2b[32], s2o[64], s2ob[2];
    __shared__ float sld;
    __shared__ float sc_cw[NLAYER][9], sc_w[NLAYER][8], sc_ch[NLAYER][9];
    __shared__ float sc_h[NLAYER][8], sc_d[NLAYER][9];
    __shared__ float sc_invW[NLAYER][4], sc_b2[NLAYER][2];
    __shared__ int   sc_perm[NLAYER][2];

    const int tid  = threadIdx.x;
    const int lane = tid & 31;

    if (tid < 32) { s1w[tid] = n1w1[tid]; s1b[tid] = n1b1[tid]; s2b[tid] = n2b1[tid]; }
    if (tid < 64) { s1o[tid] = n1w2[tid]; s2o[tid] = n2w2[tid]; }
    if (tid < 128) s2w[tid] = n2w1[tid];
    if (tid < 2)  { s1ob[tid] = n1b2[tid]; s2ob[tid] = n2b2[tid]; }
    if (tid == 0) sld = g_ldinit;
    for (int i = tid; i < NLAYER * 9; i += 256) {
        sc_cw[i / 9][i % 9] = g_cw0[i];
        sc_ch[i / 9][i % 9] = g_ch0[i];
        sc_d [i / 9][i % 9] = g_d0[i];
    }
    for (int i = tid; i < NLAYER * 8; i += 256) {
        sc_w[i / 8][i % 8] = g_w0[i];
        sc_h[i / 8][i % 8] = g_h0[i];
    }
    for (int i = tid; i < NLAYER * 4; i += 256) sc_invW[i / 4][i % 4] = g_invW[i];
    for (int i = tid; i < NLAYER * 2; i += 256) {
        sc_b2[i / 2][i % 2]   = lu_bias[i];
        sc_perm[i / 2][i % 2] = perms[i];
    }
    __syncthreads();

    const int row = blockIdx.x * 256 + tid;

    // ---- prelude (fused) ----
    float sg = sigma[row];
    float2 zv = ((const float2*)z0in)[row];
    float2 xv = ((const float2*)xin)[row];
    float t0 = s1ob[0], t1 = s1ob[1];
    #pragma unroll
    for (int j = 0; j < 32; j++) {
        float hv = s1w[j] * sg + s1b[j];
        hv = hv * __frcp_rn(1.f + __expf(-hv));
        t0 += s1o[j] * hv;
        t1 += s1o[32 + j] * hv;
    }
    float zc0 = s2ob[0], zc1 = s2ob[1];
    #pragma unroll
    for (int j = 0; j < 32; j++) {
        float hv = s2w[4 * j] * zv.x + s2w[4 * j + 1] * zv.y
                 + s2w[4 * j + 2] * xv.x + s2w[4 * j + 3] * xv.y + s2b[j];
        hv = hv * __frcp_rn(1.f + __expf(-hv));
        zc0 += s2o[j] * hv;
        zc1 += s2o[32 + j] * hv;
    }
    float z0 = zc0 + t0;
    float z1 = zc1 + t1;
    float ld = sld;

    // ---- 16 layers ----
    #pragma unroll 1
    for (int l = 0; l < NLAYER; l++) {
        float out0, ldp0;
        rqs_reg(z0, sc_cw[l], sc_w[l], sc_ch[l], sc_h[l], sc_d[l], out0, ldp0);

        float uf = (out0 - TLO_F)  * TINVD_F;
        float uc = (out0 + 16.f) * TINVD_C;
        bool useF = (uf >= 0.f) && (uf < (float)(NODES_F - 1));
        bool useC = !useF && (uc >= 0.f) && (uc < (float)(NODES_C - 1));
        bool inr  = useF || useC;

        float out1 = z1, ldp1 = 0.f;
        if (inr) {
            float u = useF ? uf : uc;
            int i = (int)u;
            float f = u - (float)i;
            size_t nidx = useF ? ((size_t)l * NODES_F + i) : ((size_t)l * NODES_C + i);
            const float* s1p = (useF ? g_s1F : g_s1C) + nidx * 12;
            const float* kdp = (useF ? g_kdF : g_kdC) + nidx * 64;

            // stage 1: lerped ch -> bin k, yk, yk1
            float4 q0 = ((const float4*)s1p)[0];
            float4 q1 = ((const float4*)s1p)[1];
            float4 q2 = ((const float4*)s1p)[2];
            float d01, d23, d45, d6x, dlo, dhi;
            float chL[9];
            chL[0] = -TBV; chL[8] = TBV;
            unpack_h2(q1.w, d01, d23);
            chL[1] = fmaf(f, d01, q0.x);
            chL[2] = fmaf(f, d23, q0.y);
            unpack_h2(q2.x, d45, d6x);
            chL[3] = fmaf(f, d45, q0.z);
            chL[4] = fmaf(f, d6x, q0.w);
            unpack_h2(q2.y, dlo, dhi);
            chL[5] = fmaf(f, dlo, q1.x);
            chL[6] = fmaf(f, dhi, q1.y);
            unpack_h2(q2.z, dlo, dhi);
            chL[7] = fmaf(f, dlo, q1.z);

            bool inside = (z1 >= -TBV) && (z1 <= TBV);
            float yc = fminf(fmaxf(z1, -TBV), TBV);
            int k = 0;
            float yk = chL[0], yk1 = chL[1];
            #pragma unroll
            for (int j = 1; j < NBINS; j++) {
                bool c = yc >= chL[j];
                k   = c ? j : k;
                yk  = c ? chL[j] : yk;
                yk1 = c ? chL[j + 1] : yk1;
            }

            // stage 2: k-indexed cw/d pair with fp16 deltas
            const float4* e = (const float4*)(kdp + k * 8);
            float4 a = e[0];
            float4 b = e[1];
            float dcl, dch_, ddl, ddh;
            unpack_h2(a.z, dcl, dch_);
            unpack_h2(b.z, ddl, ddh);
            float xk  = fmaf(f, dcl,  a.x);
            float xk1 = fmaf(f, dch_, a.y);
            float dk  = fmaf(f, ddl,  b.x);
            float dk1 = fmaf(f, ddh,  b.y);

            float hk = yk1 - yk, wk = xk1 - xk;
            float sk = __fdividef(hk, wk);
            float dy = yc - yk;
            float t2 = dk + dk1 - 2.f * sk;
            float qa = dy * t2 + hk * (sk - dk);
            float qb = hk * dk - dy * t2;
            float qc = -sk * dy;
            float disc = fmaxf(qb * qb - 4.f * qa * qc, 0.f);
            float theta = __fdividef(2.f * qc, -qb - sqrtf(disc));
            float xo = theta * wk + xk;
            float om = 1.f - theta;
            float denom = sk + t2 * theta * om;
            float dnum = sk * sk * (dk1 * theta * theta + 2.f * sk * theta * om + dk * om * om);
            float ldf = __logf(__fdividef(dnum, denom * denom));
            out1 = inside ? xo : z1;
            ldp1 = inside ? -ldf : 0.f;
        }
        unsigned need = __ballot_sync(0xffffffffu, !inr);
        if (need) {
            float p1[PMVAL];
            made_fallback(need, out0, l, made_W0, made_b0, made_Wres, made_bres,
                          made_Wf, made_bf, p1, lane);
            if (!inr) {
                float cw9[9], ch9[9], dd9[9];
                knots_from_p1(p1, cw9, ch9, dd9);
                rqs_knots(z1, cw9, ch9, dd9, out1, ldp1);
            }
        }

        ld += ldp0 + ldp1;
        float v0 = out0 - sc_b2[l][0];
        float v1 = out1 - sc_b2[l][1];
        float zz0 = sc_invW[l][0] * v0 + sc_invW[l][1] * v1;
        float zz1 = sc_invW[l][2] * v0 + sc_invW[l][3] * v1;
        z0 = sc_perm[l][0] ? zz1 : zz0;
        z1 = sc_perm[l][1] ? zz1 : zz0;
    }

    ((float2*)out)[row] = make_float2(z0, z1);
    out[2 * BATCH + row] = ld;
}

// ------------------------------ launcher -----------------------------------
extern "C" void kernel_launch(void* const* d_in, const int* in_sizes, int n_in,
                              void* d_out, int out_size) {
    const float* z0      = (const float*)d_in[0];
    const float* x       = (const float*)d_in[1];
    const float* sigma   = (const float*)d_in[2];
    const float* n1_w1   = (const float*)d_in[3];
    const float* n1_b1   = (const float*)d_in[4];
    const float* n1_w2   = (const float*)d_in[5];
    const float* n1_b2   = (const float*)d_in[6];
    const float* n2_w1   = (const float*)d_in[7];
    const float* n2_b1   = (const float*)d_in[8];
    const float* n2_w2   = (const float*)d_in[9];
    const float* n2_b2   = (const float*)d_in[10];
    const float* made_W0 = (const float*)d_in[11];
    const float* made_b0 = (const float*)d_in[12];
    const float* made_Wres = (const float*)d_in[13];
    const float* made_bres = (const float*)d_in[14];
    const float* made_Wf   = (const float*)d_in[15];
    const float* made_bf   = (const float*)d_in[16];
    const float* lu_lower  = (const float*)d_in[17];
    const float* lu_upper  = (const float*)d_in[18];
    const float* lu_diag   = (const float*)d_in[19];
    const float* lu_bias   = (const float*)d_in[20];
    const int*   perms     = (const int*)d_in[21];
    float* out = (float*)d_out;

    cudaFuncSetAttribute(table_build_kernel,
                         cudaFuncAttributeMaxDynamicSharedMemorySize, DYN_SMEM);

    build_wimg_kernel<<<64 * 20 + 16 * 8, dim3(32, 8)>>>(made_Wres, made_Wf);
    setup_kernel<<<1, 32>>>(made_bf, lu_lower, lu_upper, lu_diag);
    table_build_kernel<<<NLAYER * BLKS_PER_LAYER, 256, DYN_SMEM>>>(
        made_W0, made_b0, made_bres, made_bf);
    flow_kernel<<<BATCH / 256, 256>>>(
        z0, x, sigma, n1_w1, n1_b1, n1_w2, n1_b2,
        n2_w1, n2_b1, n2_w2, n2_b2,
        made_W0, made_b0, made_Wres, made_bres, made_Wf, made_bf,
        lu_bias, perms, out);
    (void)in_sizes; (void)n_in; (void)out_size;
}